// round 4
// baseline (speedup 1.0000x reference)
#include <cuda_runtime.h>
#include <cuda_bf16.h>
#include <math.h>

#define Bc 2
#define NH 6
#define HD 32
#define Dz 16
#define Hy 32
#define Wx 32
#define NS (Dz*Hy*Wx)      // 16384
#define CH 192
#define SCALE 0.17677669529663687f

// Output regions (tuple concat): out, offs, offset_mag, branch_energy, guide
#define O_OUT   0
#define O_OFFS  6291456     // 2*192*16384
#define O_MAG   6881280     // + 2*6*16384*3
#define O_EN    6881292
#define O_GUIDE 6881296

// Scratch (device globals; allocation-free)
__device__ float g_qT[Bc*NH*NS*HD];
__device__ float g_kT[Bc*NH*NS*HD];
__device__ float g_vT[Bc*NH*NS*HD];
__device__ float g_tT[Bc*NH*NS*HD];
__device__ float g_lepeT[Bc*NH*NS*HD];
__device__ float g_attnT[Bc*NH*NS*HD];
__device__ float g_offs[Bc*NH*NS*3];
__device__ float g_mag[Bc*NH];
__device__ float g_energy[Bc*2];

__device__ __forceinline__ float warpSum(float v) {
#pragma unroll
    for (int o = 16; o; o >>= 1) v += __shfl_xor_sync(0xffffffffu, v, o);
    return v;
}

// ---------------- zero accumulators ----------------
__global__ void k_zero() {
    int t = threadIdx.x;
    if (t < Bc*NH) g_mag[t] = 0.f;
    if (t < Bc*2)  g_energy[t] = 0.f;
}

// ---------------- conv1x1 (qkv) : X[b,c,s] x W[o,c] -> T layout [b,h,s,hd] ----------------
__global__ void k_conv1x1_qkv(const float* __restrict__ X, const float* __restrict__ W,
                              const float* __restrict__ bias, int sel)
{
    float* outT = (sel == 0) ? g_qT : (sel == 1) ? g_kT : g_vT;
    const int b  = blockIdx.z;
    const int o0 = blockIdx.y * 64;
    const int s0 = blockIdx.x * 64;
    const int tx = threadIdx.x, ty = threadIdx.y;
    const int tid = ty * 16 + tx;

    __shared__ float sW[64][17];
    __shared__ float sX[16][64];
    __shared__ float sC[64][65];

    float acc[4][4] = {};
    const float* Xb = X + (size_t)b * CH * NS;

    for (int kk = 0; kk < CH; kk += 16) {
#pragma unroll
        for (int l = 0; l < 4; l++) {
            int idx = tid + l * 256;
            int r = idx >> 4, c = idx & 15;
            sW[r][c] = W[(o0 + r) * CH + kk + c];
        }
#pragma unroll
        for (int l = 0; l < 4; l++) {
            int idx = tid + l * 256;
            int r = idx >> 6, c = idx & 63;
            sX[r][c] = Xb[(size_t)(kk + r) * NS + s0 + c];
        }
        __syncthreads();
#pragma unroll
        for (int k = 0; k < 16; k++) {
            float a[4], bq[4];
#pragma unroll
            for (int i = 0; i < 4; i++) a[i] = sW[ty + 16 * i][k];
#pragma unroll
            for (int j = 0; j < 4; j++) bq[j] = sX[k][tx + 16 * j];
#pragma unroll
            for (int i = 0; i < 4; i++)
#pragma unroll
                for (int j = 0; j < 4; j++) acc[i][j] += a[i] * bq[j];
        }
        __syncthreads();
    }
#pragma unroll
    for (int i = 0; i < 4; i++) {
        float bv = bias[o0 + ty + 16 * i];
#pragma unroll
        for (int j = 0; j < 4; j++) sC[ty + 16 * i][tx + 16 * j] = acc[i][j] + bv;
    }
    __syncthreads();
#pragma unroll
    for (int it = 0; it < 16; ++it) {
        int idx = tid + it * 256;
        int sl = idx >> 6, ol = idx & 63;
        int o = o0 + ol;
        outT[(((size_t)b * NH + (o >> 5)) * NS + (s0 + sl)) * HD + (o & 31)] = sC[ol][sl];
    }
}

// ---------------- depthwise 3x3x3 : qT -> tT (odw) & lepeT (rpew) ----------------
__global__ void k_dwconv(const float* __restrict__ odw, const float* __restrict__ odb,
                         const float* __restrict__ rpew, const float* __restrict__ rpeb)
{
    const int bh = blockIdx.y;
    const int h = bh % NH;
    const int lane = threadIdx.x & 31, wid = threadIdx.x >> 5;

    __shared__ float sWt[27][32];
    __shared__ float sWl[27][32];
    for (int idx = threadIdx.x; idx < 27 * 32; idx += 256) {
        int c = idx & 31, tap = idx >> 5;
        sWt[tap][c] = odw[(h * 32 + c) * 27 + tap];
        sWl[tap][c] = rpew[(h * 32 + c) * 27 + tap];
    }
    __syncthreads();

    const float bt = odb[h * 32 + lane];
    const float bl = rpeb[h * 32 + lane];
    const float* base = g_qT + (size_t)bh * NS * HD;

    for (int p = 0; p < 8; p++) {
        int s = blockIdx.x * 64 + wid * 8 + p;
        int z = s >> 10, y = (s >> 5) & 31, x = s & 31;
        float at = bt, al = bl;
#pragma unroll
        for (int kd = 0; kd < 3; kd++) {
            int zz = z + kd - 1;
            if ((unsigned)zz >= (unsigned)Dz) continue;
#pragma unroll
            for (int kh = 0; kh < 3; kh++) {
                int yy = y + kh - 1;
                if ((unsigned)yy >= (unsigned)Hy) continue;
#pragma unroll
                for (int kw = 0; kw < 3; kw++) {
                    int xx = x + kw - 1;
                    if ((unsigned)xx >= (unsigned)Wx) continue;
                    float v = base[(size_t)(zz * 1024 + yy * 32 + xx) * 32 + lane];
                    int tap = (kd * 3 + kh) * 3 + kw;
                    at += v * sWt[tap][lane];
                    al += v * sWl[tap][lane];
                }
            }
        }
        size_t oi = ((size_t)bh * NS + s) * 32 + lane;
        g_tT[oi] = at;
        g_lepeT[oi] = al;
    }
}

// ---------------- LN + GELU + offset conv (18) + tanh*scale ----------------
__global__ void k_offsets(const float* __restrict__ lnw, const float* __restrict__ lnb,
                          const float* __restrict__ opw, const float* __restrict__ opb,
                          float* __restrict__ d_out)
{
    __shared__ float sOp[18 * 192];
    __shared__ float sLn[2][192];
    for (int i = threadIdx.x; i < 18 * 192; i += 256) sOp[i] = opw[i];
    for (int i = threadIdx.x; i < 192; i += 256) { sLn[0][i] = lnw[i]; sLn[1][i] = lnb[i]; }
    __syncthreads();

    const int lane = threadIdx.x & 31, wid = threadIdx.x >> 5;
    const int gid = blockIdx.x * 8 + wid;      // over B*NS
    const int b = gid >> 14;
    const int s = gid & (NS - 1);

    float v[6];
#pragma unroll
    for (int h = 0; h < 6; h++) v[h] = g_tT[(((size_t)b * 6 + h) * NS + s) * 32 + lane];

    float sm = 0.f;
#pragma unroll
    for (int h = 0; h < 6; h++) sm += v[h];
    sm = warpSum(sm);
    float mean = sm * (1.f / 192.f);
    float s2 = 0.f;
#pragma unroll
    for (int h = 0; h < 6; h++) { float d = v[h] - mean; s2 += d * d; }
    s2 = warpSum(s2);
    float inv = rsqrtf(s2 * (1.f / 192.f) + 1e-5f);

    float g[6];
#pragma unroll
    for (int h = 0; h < 6; h++) {
        int c = h * 32 + lane;
        float n = (v[h] - mean) * inv * sLn[0][c] + sLn[1][c];
        g[h] = 0.5f * n * (1.f + erff(n * 0.70710678118654752f));
    }

    float mine = 0.f;
    for (int o = 0; o < 18; o++) {
        float p = 0.f;
#pragma unroll
        for (int h = 0; h < 6; h++) p += g[h] * sOp[o * 192 + h * 32 + lane];
        p = warpSum(p);
        if (lane == o) mine = p;
    }

    float ov = 0.f;
    if (lane < 18) {
        float val = tanhf(mine + opb[lane]);
        int comp = lane % 3;
        float sc = (comp == 2) ? (2.f / 15.f) : (2.f / 31.f);
        ov = val * sc;
        int h = lane / 3;
        size_t oi = (((size_t)b * 6 + h) * NS + s) * 3 + comp;
        g_offs[oi] = ov;
        d_out[O_OFFS + oi] = ov;
    }
    // offset magnitude per head
    float ox = __shfl_sync(0xffffffffu, ov, (lane < 6) ? 3 * lane : 0);
    float oy = __shfl_sync(0xffffffffu, ov, (lane < 6) ? 3 * lane + 1 : 0);
    float oz = __shfl_sync(0xffffffffu, ov, (lane < 6) ? 3 * lane + 2 : 0);
    if (lane < 6) atomicAdd(&g_mag[b * 6 + lane], sqrtf(ox * ox + oy * oy + oz * oz));
}

// ---------------- deformable attention ----------------
__global__ void k_attn(const float* __restrict__ bias0, const float* __restrict__ bias1)
{
    const int bh = blockIdx.y;
    const int b = bh / NH, h = bh % NH;
    const int bi = (h >= 3) ? 1 : 0;
    const int dil = bi ? 2 : 1;
    const float* bias = bi ? (bias1 + (h - 3) * 27) : (bias0 + h * 27);

    const int lane = threadIdx.x & 31, wid = threadIdx.x >> 5;
    const int s = blockIdx.x * 8 + wid;
    const int z = s >> 10, y = (s >> 5) & 31, x = s & 31;

    const size_t qi = ((size_t)bh * NS + s) * 32 + lane;
    const float q = g_qT[qi];
    const float* ob = g_offs + ((size_t)bh * NS + s) * 3;
    const float bx = (float)x + ob[0] * 15.5f;
    const float by = (float)y + ob[1] * 15.5f;
    const float bz = (float)z + ob[2] * 7.5f;

    const float* kb = g_kT + (size_t)bh * NS * 32;
    const float* vb = g_vT + (size_t)bh * NS * 32;

    float m = -1e30f, l = 0.f, acc = 0.f;
#pragma unroll 1
    for (int j = 0; j < 27; j++) {
        int rx = (j % 3 - 1) * dil;
        int ry = ((j / 3) % 3 - 1) * dil;
        int rz = (j / 9 - 1) * dil;
        float px = fminf(fmaxf(bx + rx, 0.f), 31.f);
        float py = fminf(fmaxf(by + ry, 0.f), 31.f);
        float pz = fminf(fmaxf(bz + rz, 0.f), 15.f);
        float fx = floorf(px), fy = floorf(py), fz = floorf(pz);
        int x0 = (int)fx, y0 = (int)fy, z0 = (int)fz;
        int x1 = min(x0 + 1, 31), y1 = min(y0 + 1, 31), z1 = min(z0 + 1, 15);
        float wx = px - fx, wy = py - fy, wz = pz - fz;
        float ux = 1.f - wx, uy = 1.f - wy, uz = 1.f - wz;

        int i000 = ((z0 * 32 + y0) * 32 + x0) * 32 + lane;
        int i001 = ((z0 * 32 + y0) * 32 + x1) * 32 + lane;
        int i010 = ((z0 * 32 + y1) * 32 + x0) * 32 + lane;
        int i011 = ((z0 * 32 + y1) * 32 + x1) * 32 + lane;
        int i100 = ((z1 * 32 + y0) * 32 + x0) * 32 + lane;
        int i101 = ((z1 * 32 + y0) * 32 + x1) * 32 + lane;
        int i110 = ((z1 * 32 + y1) * 32 + x0) * 32 + lane;
        int i111 = ((z1 * 32 + y1) * 32 + x1) * 32 + lane;

        float w000 = uz * uy * ux, w001 = uz * uy * wx;
        float w010 = uz * wy * ux, w011 = uz * wy * wx;
        float w100 = wz * uy * ux, w101 = wz * uy * wx;
        float w110 = wz * wy * ux, w111 = wz * wy * wx;

        float ks = w000 * kb[i000] + w001 * kb[i001] + w010 * kb[i010] + w011 * kb[i011]
                 + w100 * kb[i100] + w101 * kb[i101] + w110 * kb[i110] + w111 * kb[i111];
        float sc = warpSum(q * ks) * SCALE + bias[j];

        float mn = fmaxf(m, sc);
        float corr = __expf(m - mn);
        float p = __expf(sc - mn);
        l = l * corr + p;

        float vs = w000 * vb[i000] + w001 * vb[i001] + w010 * vb[i010] + w011 * vb[i011]
                 + w100 * vb[i100] + w101 * vb[i101] + w110 * vb[i110] + w111 * vb[i111];
        acc = acc * corr + p * vs;
        m = mn;
    }
    float res = acc / l;
    g_attnT[qi] = res + g_lepeT[qi];

    // branch energy (pre-lepe)
    float e = warpSum(fabsf(res));
    __shared__ float sE[8];
    if (lane == 0) sE[wid] = e;
    __syncthreads();
    if (threadIdx.x == 0) {
        float t = 0.f;
#pragma unroll
        for (int i = 0; i < 8; i++) t += sE[i];
        atomicAdd(&g_energy[b * 2 + bi], t);
    }
}

// ---------------- final conv1x1 : (attn+lepe)[T layout] x pw -> d_out [b,c,s] ----------------
__global__ void k_conv1x1_final(const float* __restrict__ W, const float* __restrict__ bias,
                                float* __restrict__ out)
{
    const int b  = blockIdx.z;
    const int o0 = blockIdx.y * 64;
    const int s0 = blockIdx.x * 64;
    const int tx = threadIdx.x, ty = threadIdx.y;
    const int tid = ty * 16 + tx;

    __shared__ float sW[64][17];
    __shared__ float sX[16][64];
    float acc[4][4] = {};

    for (int kk = 0; kk < CH; kk += 16) {
#pragma unroll
        for (int l = 0; l < 4; l++) {
            int idx = tid + l * 256;
            int r = idx >> 4, c = idx & 15;
            sW[r][c] = W[(o0 + r) * CH + kk + c];
        }
#pragma unroll
        for (int l = 0; l < 4; l++) {
            int idx = tid + l * 256;
            int r = idx >> 6, c = idx & 63;
            int ch = kk + r;
            sX[r][c] = g_attnT[(((size_t)b * NH + (ch >> 5)) * NS + (s0 + c)) * HD + (ch & 31)];
        }
        __syncthreads();
#pragma unroll
        for (int k = 0; k < 16; k++) {
            float a[4], bq[4];
#pragma unroll
            for (int i = 0; i < 4; i++) a[i] = sW[ty + 16 * i][k];
#pragma unroll
            for (int j = 0; j < 4; j++) bq[j] = sX[k][tx + 16 * j];
#pragma unroll
            for (int i = 0; i < 4; i++)
#pragma unroll
                for (int j = 0; j < 4; j++) acc[i][j] += a[i] * bq[j];
        }
        __syncthreads();
    }
#pragma unroll
    for (int i = 0; i < 4; i++) {
        int o = o0 + ty + 16 * i;
        float bv = bias[o];
#pragma unroll
        for (int j = 0; j < 4; j++) {
            out[O_OUT + (size_t)b * CH * NS + (size_t)o * NS + (s0 + tx + 16 * j)] = acc[i][j] + bv;
        }
    }
}

// ---------------- finalize small outputs ----------------
__global__ void k_finalize(float* __restrict__ out)
{
    int t = threadIdx.x;
    const float inv_sp = 1.f / (float)NS;
    const float inv_en = 1.f / (3.f * 32.f * (float)NS);
    if (t < 12) out[O_MAG + t] = g_mag[t] * inv_sp;
    if (t < 4)  out[O_EN + t] = g_energy[t] * inv_en;
    if (t < 16) {
        int b = t >> 3, j = t & 7;
        out[O_GUIDE + t] = (j < 6) ? g_mag[b * 6 + j] * inv_sp
                                   : g_energy[b * 2 + (j - 6)] * inv_en;
    }
}

extern "C" void kernel_launch(void* const* d_in, const int* in_sizes, int n_in,
                              void* d_out, int out_size)
{
    const float* x    = (const float*)d_in[0];
    const float* qw   = (const float*)d_in[1];
    const float* qb   = (const float*)d_in[2];
    const float* kw   = (const float*)d_in[3];
    const float* kbi  = (const float*)d_in[4];
    const float* vw   = (const float*)d_in[5];
    const float* vbi  = (const float*)d_in[6];
    const float* pw   = (const float*)d_in[7];
    const float* pb   = (const float*)d_in[8];
    const float* odw  = (const float*)d_in[9];
    const float* odb  = (const float*)d_in[10];
    const float* lnw  = (const float*)d_in[11];
    const float* lnb  = (const float*)d_in[12];
    const float* opw  = (const float*)d_in[13];
    const float* opb  = (const float*)d_in[14];
    const float* rpew = (const float*)d_in[15];
    const float* rpeb = (const float*)d_in[16];
    const float* b0   = (const float*)d_in[17];
    const float* b1   = (const float*)d_in[18];
    float* out = (float*)d_out;

    k_zero<<<1, 32>>>();

    dim3 gB(NS / 64, CH / 64, Bc), tB(16, 16);
    k_conv1x1_qkv<<<gB, tB>>>(x, qw, qb, 0);
    k_conv1x1_qkv<<<gB, tB>>>(x, kw, kbi, 1);
    k_conv1x1_qkv<<<gB, tB>>>(x, vw, vbi, 2);

    k_dwconv<<<dim3(NS / 64, Bc * NH), 256>>>(odw, odb, rpew, rpeb);

    k_offsets<<<dim3(Bc * NS / 8), 256>>>(lnw, lnb, opw, opb, out);

    k_attn<<<dim3(NS / 8, Bc * NH), 256>>>(b0, b1);

    k_conv1x1_final<<<gB, tB>>>(pw, pb, out);

    k_finalize<<<1, 32>>>(out);
}

// round 5
// speedup vs baseline: 1.8001x; 1.8001x over previous
#include <cuda_runtime.h>
#include <cuda_bf16.h>
#include <math.h>

#define Bc 2
#define NH 6
#define HD 32
#define Dz 16
#define Hy 32
#define Wx 32
#define NS (Dz*Hy*Wx)      // 16384
#define CH 192
#define SCALE 0.17677669529663687f

// Output regions (tuple concat): out, offs, offset_mag, branch_energy, guide
#define O_OUT   0
#define O_OFFS  6291456     // 2*192*16384
#define O_MAG   6881280     // + 2*6*16384*3
#define O_EN    6881292
#define O_GUIDE 6881296

// Scratch (device globals; allocation-free)
__device__ float  g_qT[Bc*NH*NS*HD];      // [bh][s][hd]
__device__ float2 g_kv[Bc*NH*NS*HD];      // [bh][s][hd] -> (k, v)
__device__ float  g_tT[Bc*NH*NS*HD];
__device__ float  g_lepeT[Bc*NH*NS*HD];
__device__ float  g_attnC[Bc*CH*NS];      // [b][c][s]  (attn + lepe)
__device__ float  g_offs[Bc*NH*NS*3];
__device__ float  g_mag[Bc*NH];
__device__ float  g_energy[Bc*2];

__device__ __forceinline__ float warpSum(float v) {
#pragma unroll
    for (int o = 16; o; o >>= 1) v += __shfl_xor_sync(0xffffffffu, v, o);
    return v;
}

__global__ void k_zero() {
    int t = threadIdx.x;
    if (t < Bc*NH) g_mag[t] = 0.f;
    if (t < Bc*2)  g_energy[t] = 0.f;
}

// ================= GEMM: q conv  X[b,c,s] x qw -> g_qT [bh][s][hd] =================
__global__ __launch_bounds__(256) void k_gemm_q(const float* __restrict__ X,
                                                const float* __restrict__ W,
                                                const float* __restrict__ bias)
{
    const int b  = blockIdx.z;
    const int o0 = blockIdx.y * 64;
    const int s0 = blockIdx.x * 64;
    const int tid = threadIdx.x;
    const int tx = tid & 15, ty = tid >> 4;

    __shared__ __align__(16) float sW[16][68];
    __shared__ __align__(16) float sX[16][68];
    __shared__ float sC[64][65];

    float acc[4][4] = {};
    const float* Xb = X + (size_t)b * CH * NS;

    for (int kk = 0; kk < CH; kk += 16) {
        {   // W transpose load: sW[c][o]
            int r = tid >> 2, cq = (tid & 3) * 4;
            float4 w4 = *(const float4*)&W[(o0 + r) * CH + kk + cq];
            sW[cq + 0][r] = w4.x; sW[cq + 1][r] = w4.y;
            sW[cq + 2][r] = w4.z; sW[cq + 3][r] = w4.w;
        }
        {   // X load: sX[c][s]
            int r = tid >> 4, cq = (tid & 15) * 4;
            *(float4*)&sX[r][cq] = *(const float4*)&Xb[(size_t)(kk + r) * NS + s0 + cq];
        }
        __syncthreads();
#pragma unroll
        for (int k = 0; k < 16; k++) {
            float4 av = *(const float4*)&sW[k][ty * 4];
            float4 bv = *(const float4*)&sX[k][tx * 4];
            acc[0][0] += av.x*bv.x; acc[0][1] += av.x*bv.y; acc[0][2] += av.x*bv.z; acc[0][3] += av.x*bv.w;
            acc[1][0] += av.y*bv.x; acc[1][1] += av.y*bv.y; acc[1][2] += av.y*bv.z; acc[1][3] += av.y*bv.w;
            acc[2][0] += av.z*bv.x; acc[2][1] += av.z*bv.y; acc[2][2] += av.z*bv.z; acc[2][3] += av.z*bv.w;
            acc[3][0] += av.w*bv.x; acc[3][1] += av.w*bv.y; acc[3][2] += av.w*bv.z; acc[3][3] += av.w*bv.w;
        }
        __syncthreads();
    }
#pragma unroll
    for (int i = 0; i < 4; i++) {
        float bv = bias[o0 + ty * 4 + i];
#pragma unroll
        for (int j = 0; j < 4; j++) sC[ty * 4 + i][tx * 4 + j] = acc[i][j] + bv;
    }
    __syncthreads();
#pragma unroll
    for (int it = 0; it < 16; ++it) {
        int idx = tid + it * 256;
        int sl = idx >> 6, ol = idx & 63;
        int o = o0 + ol;
        g_qT[(((size_t)b * NH + (o >> 5)) * NS + (s0 + sl)) * HD + (o & 31)] = sC[ol][sl];
    }
}

// ================= GEMM: fused k & v conv -> g_kv float2 =================
__global__ __launch_bounds__(256) void k_gemm_kv(const float* __restrict__ X,
                                                 const float* __restrict__ Wk, const float* __restrict__ bk,
                                                 const float* __restrict__ Wv, const float* __restrict__ bv_)
{
    const int b  = blockIdx.z;
    const int o0 = blockIdx.y * 64;
    const int s0 = blockIdx.x * 64;
    const int tid = threadIdx.x;
    const int tx = tid & 15, ty = tid >> 4;

    __shared__ __align__(16) float sWk[16][68];
    __shared__ __align__(16) float sWv[16][68];
    __shared__ __align__(16) float sX[16][68];
    __shared__ float2 sC2[64][65];

    float ak[4][4] = {}, av_[4][4] = {};
    const float* Xb = X + (size_t)b * CH * NS;

    for (int kk = 0; kk < CH; kk += 16) {
        {
            int r = tid >> 2, cq = (tid & 3) * 4;
            float4 w4 = *(const float4*)&Wk[(o0 + r) * CH + kk + cq];
            sWk[cq + 0][r] = w4.x; sWk[cq + 1][r] = w4.y; sWk[cq + 2][r] = w4.z; sWk[cq + 3][r] = w4.w;
            float4 v4 = *(const float4*)&Wv[(o0 + r) * CH + kk + cq];
            sWv[cq + 0][r] = v4.x; sWv[cq + 1][r] = v4.y; sWv[cq + 2][r] = v4.z; sWv[cq + 3][r] = v4.w;
        }
        {
            int r = tid >> 4, cq = (tid & 15) * 4;
            *(float4*)&sX[r][cq] = *(const float4*)&Xb[(size_t)(kk + r) * NS + s0 + cq];
        }
        __syncthreads();
#pragma unroll
        for (int k = 0; k < 16; k++) {
            float4 wa = *(const float4*)&sWk[k][ty * 4];
            float4 wb = *(const float4*)&sWv[k][ty * 4];
            float4 xv = *(const float4*)&sX[k][tx * 4];
            ak[0][0] += wa.x*xv.x; ak[0][1] += wa.x*xv.y; ak[0][2] += wa.x*xv.z; ak[0][3] += wa.x*xv.w;
            ak[1][0] += wa.y*xv.x; ak[1][1] += wa.y*xv.y; ak[1][2] += wa.y*xv.z; ak[1][3] += wa.y*xv.w;
            ak[2][0] += wa.z*xv.x; ak[2][1] += wa.z*xv.y; ak[2][2] += wa.z*xv.z; ak[2][3] += wa.z*xv.w;
            ak[3][0] += wa.w*xv.x; ak[3][1] += wa.w*xv.y; ak[3][2] += wa.w*xv.z; ak[3][3] += wa.w*xv.w;
            av_[0][0] += wb.x*xv.x; av_[0][1] += wb.x*xv.y; av_[0][2] += wb.x*xv.z; av_[0][3] += wb.x*xv.w;
            av_[1][0] += wb.y*xv.x; av_[1][1] += wb.y*xv.y; av_[1][2] += wb.y*xv.z; av_[1][3] += wb.y*xv.w;
            av_[2][0] += wb.z*xv.x; av_[2][1] += wb.z*xv.y; av_[2][2] += wb.z*xv.z; av_[2][3] += wb.z*xv.w;
            av_[3][0] += wb.w*xv.x; av_[3][1] += wb.w*xv.y; av_[3][2] += wb.w*xv.z; av_[3][3] += wb.w*xv.w;
        }
        __syncthreads();
    }
#pragma unroll
    for (int i = 0; i < 4; i++) {
        int o = o0 + ty * 4 + i;
        float bkk = bk[o], bvv = bv_[o];
#pragma unroll
        for (int j = 0; j < 4; j++)
            sC2[ty * 4 + i][tx * 4 + j] = make_float2(ak[i][j] + bkk, av_[i][j] + bvv);
    }
    __syncthreads();
#pragma unroll
    for (int it = 0; it < 16; ++it) {
        int idx = tid + it * 256;
        int sl = idx >> 6, ol = idx & 63;
        int o = o0 + ol;
        g_kv[(((size_t)b * NH + (o >> 5)) * NS + (s0 + sl)) * HD + (o & 31)] = sC2[ol][sl];
    }
}

// ================= depthwise 3x3x3 on qT -> tT & lepeT =================
__global__ void k_dwconv(const float* __restrict__ odw, const float* __restrict__ odb,
                         const float* __restrict__ rpew, const float* __restrict__ rpeb)
{
    const int bh = blockIdx.y;
    const int h = bh % NH;
    const int lane = threadIdx.x & 31, wid = threadIdx.x >> 5;

    __shared__ float sWt[27][32];
    __shared__ float sWl[27][32];
    for (int idx = threadIdx.x; idx < 27 * 32; idx += 256) {
        int c = idx & 31, tap = idx >> 5;
        sWt[tap][c] = odw[(h * 32 + c) * 27 + tap];
        sWl[tap][c] = rpew[(h * 32 + c) * 27 + tap];
    }
    __syncthreads();

    const float bt = odb[h * 32 + lane];
    const float bl = rpeb[h * 32 + lane];
    const float* base = g_qT + (size_t)bh * NS * HD;

    for (int p = 0; p < 8; p++) {
        int s = blockIdx.x * 64 + wid * 8 + p;
        int z = s >> 10, y = (s >> 5) & 31, x = s & 31;
        float at = bt, al = bl;
#pragma unroll
        for (int kd = 0; kd < 3; kd++) {
            int zz = z + kd - 1;
            if ((unsigned)zz >= (unsigned)Dz) continue;
#pragma unroll
            for (int kh = 0; kh < 3; kh++) {
                int yy = y + kh - 1;
                if ((unsigned)yy >= (unsigned)Hy) continue;
#pragma unroll
                for (int kw = 0; kw < 3; kw++) {
                    int xx = x + kw - 1;
                    if ((unsigned)xx >= (unsigned)Wx) continue;
                    float v = base[(size_t)(zz * 1024 + yy * 32 + xx) * 32 + lane];
                    int tap = (kd * 3 + kh) * 3 + kw;
                    at += v * sWt[tap][lane];
                    al += v * sWl[tap][lane];
                }
            }
        }
        size_t oi = ((size_t)bh * NS + s) * 32 + lane;
        g_tT[oi] = at;
        g_lepeT[oi] = al;
    }
}

// ================= LN + GELU + offset conv + tanh*scale =================
__global__ void k_offsets(const float* __restrict__ lnw, const float* __restrict__ lnb,
                          const float* __restrict__ opw, const float* __restrict__ opb,
                          float* __restrict__ d_out)
{
    __shared__ float sOp[18 * 192];
    __shared__ float sLn[2][192];
    for (int i = threadIdx.x; i < 18 * 192; i += 256) sOp[i] = opw[i];
    for (int i = threadIdx.x; i < 192; i += 256) { sLn[0][i] = lnw[i]; sLn[1][i] = lnb[i]; }
    __syncthreads();

    const int lane = threadIdx.x & 31, wid = threadIdx.x >> 5;
    const int gid = blockIdx.x * 8 + wid;
    const int b = gid >> 14;
    const int s = gid & (NS - 1);

    float v[6];
#pragma unroll
    for (int h = 0; h < 6; h++) v[h] = g_tT[(((size_t)b * 6 + h) * NS + s) * 32 + lane];

    float sm = 0.f;
#pragma unroll
    for (int h = 0; h < 6; h++) sm += v[h];
    sm = warpSum(sm);
    float mean = sm * (1.f / 192.f);
    float s2 = 0.f;
#pragma unroll
    for (int h = 0; h < 6; h++) { float d = v[h] - mean; s2 += d * d; }
    s2 = warpSum(s2);
    float inv = rsqrtf(s2 * (1.f / 192.f) + 1e-5f);

    float g[6];
#pragma unroll
    for (int h = 0; h < 6; h++) {
        int c = h * 32 + lane;
        float n = (v[h] - mean) * inv * sLn[0][c] + sLn[1][c];
        g[h] = 0.5f * n * (1.f + erff(n * 0.70710678118654752f));
    }

    float mine = 0.f;
    for (int o = 0; o < 18; o++) {
        float p = 0.f;
#pragma unroll
        for (int h = 0; h < 6; h++) p += g[h] * sOp[o * 192 + h * 32 + lane];
        p = warpSum(p);
        if (lane == o) mine = p;
    }

    float ov = 0.f;
    if (lane < 18) {
        float val = tanhf(mine + opb[lane]);
        int comp = lane % 3;
        float sc = (comp == 2) ? (2.f / 15.f) : (2.f / 31.f);
        ov = val * sc;
        int h = lane / 3;
        size_t oi = (((size_t)b * 6 + h) * NS + s) * 3 + comp;
        g_offs[oi] = ov;
        d_out[O_OFFS + oi] = ov;
    }
    float ox = __shfl_sync(0xffffffffu, ov, (lane < 6) ? 3 * lane : 0);
    float oy = __shfl_sync(0xffffffffu, ov, (lane < 6) ? 3 * lane + 1 : 0);
    float oz = __shfl_sync(0xffffffffu, ov, (lane < 6) ? 3 * lane + 2 : 0);
    if (lane < 6) atomicAdd(&g_mag[b * 6 + lane], sqrtf(ox * ox + oy * oy + oz * oz));
}

// ================= attention epilogue (shared by both branches) =================
__device__ __forceinline__ void attn_epilogue(float res, int b, int h, int bi,
                                              int lane, int wid, int s0b, size_t qi)
{
    float outv = res + g_lepeT[qi];
    __shared__ float sT[8][33];
    __shared__ float sE[8];
    sT[wid][lane] = outv;
    float e = warpSum(fabsf(res));
    if (lane == 0) sE[wid] = e;
    __syncthreads();
    int ch = threadIdx.x >> 3, si = threadIdx.x & 7;
    g_attnC[((size_t)b * CH + h * 32 + ch) * NS + s0b + si] = sT[si][ch];
    if (threadIdx.x == 0) {
        float t = 0.f;
#pragma unroll
        for (int i = 0; i < 8; i++) t += sE[i];
        atomicAdd(&g_energy[b * 2 + bi], t);
    }
}

// ================= attention branch 0 (dil=1): shared 4x4x4 lattice =================
__global__ __launch_bounds__(256) void k_attn1(const float* __restrict__ bias0)
{
    const int bhh = blockIdx.y;
    const int b = bhh / 3, hh = bhh % 3;
    const int h = hh;
    const int bh = b * NH + h;
    const float* bias = bias0 + hh * 27;

    const int lane = threadIdx.x & 31, wid = threadIdx.x >> 5;
    const int s0b = blockIdx.x * 8;
    const int s = s0b + wid;
    const int z = s >> 10, y = (s >> 5) & 31, x = s & 31;

    const size_t qi = ((size_t)bh * NS + s) * 32 + lane;
    const float q = g_qT[qi];
    const float* ob = g_offs + ((size_t)bh * NS + s) * 3;
    const float bx = (float)x + ob[0] * 15.5f;
    const float by = (float)y + ob[1] * 15.5f;
    const float bz = (float)z + ob[2] * 7.5f;

    const float2* __restrict__ kv = g_kv + (size_t)bh * NS * HD;

    float fx = floorf(bx), fy = floorf(by), fz = floorf(bz);
    int X0 = (int)fx, Y0 = (int)fy, Z0 = (int)fz;
    float wx = bx - fx, wy = by - fy, wz = bz - fz;
    float uz = 1.f - wz;

    int LXo[4], LYo[4], LZo[4];
#pragma unroll
    for (int t = 0; t < 4; t++) {
        LXo[t] = min(max(X0 - 1 + t, 0), 31) * 32 + lane;
        LYo[t] = min(max(Y0 - 1 + t, 0), 31) * 1024;
        LZo[t] = min(max(Z0 - 1 + t, 0), 15) * 32768;
    }

    float2 zacc[27];
#pragma unroll
    for (int j = 0; j < 27; j++) zacc[j] = make_float2(0.f, 0.f);

#pragma unroll
    for (int tz = 0; tz < 4; tz++) {
        float2 P[4][4];
#pragma unroll
        for (int ty = 0; ty < 4; ty++)
#pragma unroll
            for (int tx = 0; tx < 4; tx++)
                P[ty][tx] = kv[LZo[tz] + LYo[ty] + LXo[tx]];
        // x-lerp
        float2 A[4][3];
#pragma unroll
        for (int ty = 0; ty < 4; ty++)
#pragma unroll
            for (int jx = 0; jx < 3; jx++) {
                A[ty][jx].x = P[ty][jx].x + wx * (P[ty][jx + 1].x - P[ty][jx].x);
                A[ty][jx].y = P[ty][jx].y + wx * (P[ty][jx + 1].y - P[ty][jx].y);
            }
        // y-lerp
        float2 Bv[3][3];
#pragma unroll
        for (int jy = 0; jy < 3; jy++)
#pragma unroll
            for (int jx = 0; jx < 3; jx++) {
                Bv[jy][jx].x = A[jy][jx].x + wy * (A[jy + 1][jx].x - A[jy][jx].x);
                Bv[jy][jx].y = A[jy][jx].y + wy * (A[jy + 1][jx].y - A[jy][jx].y);
            }
        // z-accumulate
        if (tz < 3) {
#pragma unroll
            for (int r = 0; r < 9; r++) {
                zacc[tz * 9 + r].x += uz * Bv[r / 3][r % 3].x;
                zacc[tz * 9 + r].y += uz * Bv[r / 3][r % 3].y;
            }
        }
        if (tz > 0) {
#pragma unroll
            for (int r = 0; r < 9; r++) {
                zacc[(tz - 1) * 9 + r].x += wz * Bv[r / 3][r % 3].x;
                zacc[(tz - 1) * 9 + r].y += wz * Bv[r / 3][r % 3].y;
            }
        }
    }

    float sc[27];
#pragma unroll
    for (int j = 0; j < 27; j++) sc[j] = q * zacc[j].x;
    // stage-major butterfly: 27 independent reductions, pipelined
#pragma unroll
    for (int o = 16; o; o >>= 1)
#pragma unroll
        for (int j = 0; j < 27; j++) sc[j] += __shfl_xor_sync(0xffffffffu, sc[j], o);

    float m = -1e30f;
#pragma unroll
    for (int j = 0; j < 27; j++) { sc[j] = sc[j] * SCALE + bias[j]; m = fmaxf(m, sc[j]); }
    float l = 0.f, acc = 0.f;
#pragma unroll
    for (int j = 0; j < 27; j++) {
        float p = __expf(sc[j] - m);
        l += p;
        acc += p * zacc[j].y;
    }
    attn_epilogue(acc / l, b, h, 0, lane, wid, s0b, qi);
}

// ================= attention branch 1 (dil=2): direct 8-corner =================
__global__ __launch_bounds__(256) void k_attn2(const float* __restrict__ bias1)
{
    const int bhh = blockIdx.y;
    const int b = bhh / 3, hh = bhh % 3;
    const int h = hh + 3;
    const int bh = b * NH + h;
    const float* bias = bias1 + hh * 27;

    const int lane = threadIdx.x & 31, wid = threadIdx.x >> 5;
    const int s0b = blockIdx.x * 8;
    const int s = s0b + wid;
    const int z = s >> 10, y = (s >> 5) & 31, x = s & 31;

    const size_t qi = ((size_t)bh * NS + s) * 32 + lane;
    const float q = g_qT[qi];
    const float* ob = g_offs + ((size_t)bh * NS + s) * 3;
    const float bx = (float)x + ob[0] * 15.5f;
    const float by = (float)y + ob[1] * 15.5f;
    const float bz = (float)z + ob[2] * 7.5f;

    const float2* __restrict__ kv = g_kv + (size_t)bh * NS * HD;

    float sc[27], vs[27];
#pragma unroll
    for (int j = 0; j < 27; j++) {
        const int rx = (j % 3 - 1) * 2;
        const int ry = ((j / 3) % 3 - 1) * 2;
        const int rz = (j / 9 - 1) * 2;
        float px = fminf(fmaxf(bx + rx, 0.f), 31.f);
        float py = fminf(fmaxf(by + ry, 0.f), 31.f);
        float pz = fminf(fmaxf(bz + rz, 0.f), 15.f);
        float fx = floorf(px), fy = floorf(py), fz = floorf(pz);
        int x0 = (int)fx, y0 = (int)fy, z0 = (int)fz;
        int x1 = min(x0 + 1, 31), y1 = min(y0 + 1, 31), z1 = min(z0 + 1, 15);
        float wx = px - fx, wy = py - fy, wz = pz - fz;
        float ux = 1.f - wx, uy = 1.f - wy, uz = 1.f - wz;

        int r00 = (z0 * 32 + y0) * 1024, r01 = (z0 * 32 + y1) * 1024;
        int r10 = (z1 * 32 + y0) * 1024, r11 = (z1 * 32 + y1) * 1024;
        int cx0 = x0 * 32 + lane, cx1 = x1 * 32 + lane;

        float2 c000 = kv[r00 + cx0], c001 = kv[r00 + cx1];
        float2 c010 = kv[r01 + cx0], c011 = kv[r01 + cx1];
        float2 c100 = kv[r10 + cx0], c101 = kv[r10 + cx1];
        float2 c110 = kv[r11 + cx0], c111 = kv[r11 + cx1];

        float w00 = uz * uy, w01 = uz * wy, w10 = wz * uy, w11 = wz * wy;
        float w000 = w00 * ux, w001 = w00 * wx, w010 = w01 * ux, w011 = w01 * wx;
        float w100 = w10 * ux, w101 = w10 * wx, w110 = w11 * ux, w111 = w11 * wx;

        float ks = w000 * c000.x + w001 * c001.x + w010 * c010.x + w011 * c011.x
                 + w100 * c100.x + w101 * c101.x + w110 * c110.x + w111 * c111.x;
        float vv = w000 * c000.y + w001 * c001.y + w010 * c010.y + w011 * c011.y
                 + w100 * c100.y + w101 * c101.y + w110 * c110.y + w111 * c111.y;
        sc[j] = q * ks;
        vs[j] = vv;
    }
#pragma unroll
    for (int o = 16; o; o >>= 1)
#pragma unroll
        for (int j = 0; j < 27; j++) sc[j] += __shfl_xor_sync(0xffffffffu, sc[j], o);

    float m = -1e30f;
#pragma unroll
    for (int j = 0; j < 27; j++) { sc[j] = sc[j] * SCALE + bias[j]; m = fmaxf(m, sc[j]); }
    float l = 0.f, acc = 0.f;
#pragma unroll
    for (int j = 0; j < 27; j++) {
        float p = __expf(sc[j] - m);
        l += p;
        acc += p * vs[j];
    }
    attn_epilogue(acc / l, b, h, 1, lane, wid, s0b, qi);
}

// ================= final conv: g_attnC [b,c,s] x pw -> out [b,c,s] =================
__global__ __launch_bounds__(256) void k_gemm_final(const float* __restrict__ W,
                                                    const float* __restrict__ bias,
                                                    float* __restrict__ out)
{
    const int b  = blockIdx.z;
    const int o0 = blockIdx.y * 64;
    const int s0 = blockIdx.x * 64;
    const int tid = threadIdx.x;
    const int tx = tid & 15, ty = tid >> 4;

    __shared__ __align__(16) float sW[16][68];
    __shared__ __align__(16) float sX[16][68];

    float acc[4][4] = {};
    const float* Xb = g_attnC + (size_t)b * CH * NS;

    for (int kk = 0; kk < CH; kk += 16) {
        {
            int r = tid >> 2, cq = (tid & 3) * 4;
            float4 w4 = *(const float4*)&W[(o0 + r) * CH + kk + cq];
            sW[cq + 0][r] = w4.x; sW[cq + 1][r] = w4.y;
            sW[cq + 2][r] = w4.z; sW[cq + 3][r] = w4.w;
        }
        {
            int r = tid >> 4, cq = (tid & 15) * 4;
            *(float4*)&sX[r][cq] = *(const float4*)&Xb[(size_t)(kk + r) * NS + s0 + cq];
        }
        __syncthreads();
#pragma unroll
        for (int k = 0; k < 16; k++) {
            float4 av = *(const float4*)&sW[k][ty * 4];
            float4 bv = *(const float4*)&sX[k][tx * 4];
            acc[0][0] += av.x*bv.x; acc[0][1] += av.x*bv.y; acc[0][2] += av.x*bv.z; acc[0][3] += av.x*bv.w;
            acc[1][0] += av.y*bv.x; acc[1][1] += av.y*bv.y; acc[1][2] += av.y*bv.z; acc[1][3] += av.y*bv.w;
            acc[2][0] += av.z*bv.x; acc[2][1] += av.z*bv.y; acc[2][2] += av.z*bv.z; acc[2][3] += av.z*bv.w;
            acc[3][0] += av.w*bv.x; acc[3][1] += av.w*bv.y; acc[3][2] += av.w*bv.z; acc[3][3] += av.w*bv.w;
        }
        __syncthreads();
    }
#pragma unroll
    for (int i = 0; i < 4; i++) {
        int o = o0 + ty * 4 + i;
        float bv = bias[o];
        float4 r = make_float4(acc[i][0] + bv, acc[i][1] + bv, acc[i][2] + bv, acc[i][3] + bv);
        *(float4*)&out[O_OUT + ((size_t)b * CH + o) * NS + s0 + tx * 4] = r;
    }
}

__global__ void k_finalize(float* __restrict__ out)
{
    int t = threadIdx.x;
    const float inv_sp = 1.f / (float)NS;
    const float inv_en = 1.f / (3.f * 32.f * (float)NS);
    if (t < 12) out[O_MAG + t] = g_mag[t] * inv_sp;
    if (t < 4)  out[O_EN + t] = g_energy[t] * inv_en;
    if (t < 16) {
        int b = t >> 3, j = t & 7;
        out[O_GUIDE + t] = (j < 6) ? g_mag[b * 6 + j] * inv_sp
                                   : g_energy[b * 2 + (j - 6)] * inv_en;
    }
}

extern "C" void kernel_launch(void* const* d_in, const int* in_sizes, int n_in,
                              void* d_out, int out_size)
{
    const float* x    = (const float*)d_in[0];
    const float* qw   = (const float*)d_in[1];
    const float* qb   = (const float*)d_in[2];
    const float* kw   = (const float*)d_in[3];
    const float* kbi  = (const float*)d_in[4];
    const float* vw   = (const float*)d_in[5];
    const float* vbi  = (const float*)d_in[6];
    const float* pw   = (const float*)d_in[7];
    const float* pb   = (const float*)d_in[8];
    const float* odw  = (const float*)d_in[9];
    const float* odb  = (const float*)d_in[10];
    const float* lnw  = (const float*)d_in[11];
    const float* lnb  = (const float*)d_in[12];
    const float* opw  = (const float*)d_in[13];
    const float* opb  = (const float*)d_in[14];
    const float* rpew = (const float*)d_in[15];
    const float* rpeb = (const float*)d_in[16];
    const float* b0   = (const float*)d_in[17];
    const float* b1   = (const float*)d_in[18];
    float* out = (float*)d_out;

    k_zero<<<1, 32>>>();

    dim3 gG(NS / 64, CH / 64, Bc);
    k_gemm_q<<<gG, 256>>>(x, qw, qb);
    k_gemm_kv<<<gG, 256>>>(x, kw, kbi, vw, vbi);

    k_dwconv<<<dim3(NS / 64, Bc * NH), 256>>>(odw, odb, rpew, rpeb);
    k_offsets<<<dim3(Bc * NS / 8), 256>>>(lnw, lnb, opw, opb, out);

    k_attn1<<<dim3(NS / 8, Bc * 3), 256>>>(b0);
    k_attn2<<<dim3(NS / 8, Bc * 3), 256>>>(b1);

    k_gemm_final<<<gG, 256>>>(pw, pb, out);
    k_finalize<<<1, 32>>>(out);
}

// round 6
// speedup vs baseline: 1.8866x; 1.0481x over previous
#include <cuda_runtime.h>
#include <cuda_bf16.h>
#include <cuda_fp16.h>
#include <math.h>

#define Bc 2
#define NH 6
#define HD 32
#define Dz 16
#define Hy 32
#define Wx 32
#define NS (Dz*Hy*Wx)      // 16384
#define CH 192
#define SCALE 0.17677669529663687f

// Output regions (tuple concat): out, offs, offset_mag, branch_energy, guide
#define O_OUT   0
#define O_OFFS  6291456     // 2*192*16384
#define O_MAG   6881280     // + 2*6*16384*3
#define O_EN    6881292
#define O_GUIDE 6881296

// Scratch (device globals; allocation-free)
__device__ float   g_qT[Bc*NH*NS*HD];      // [bh][s][hd]
__device__ __half2 g_kvh[Bc*NH*NS*HD];     // [bh][s][hd] -> (k, v) fp16
__device__ float   g_tT[Bc*NH*NS*HD];
__device__ float   g_lepeT[Bc*NH*NS*HD];
__device__ float   g_attnC[Bc*CH*NS];      // [b][c][s]  (attn + lepe)
__device__ float   g_offs[Bc*NH*NS*3];
__device__ float   g_mag[Bc*NH];
__device__ float   g_energy[Bc*2];

__device__ __forceinline__ float warpSum(float v) {
#pragma unroll
    for (int o = 16; o; o >>= 1) v += __shfl_xor_sync(0xffffffffu, v, o);
    return v;
}

__global__ void k_zero() {
    int t = threadIdx.x;
    if (t < Bc*NH) g_mag[t] = 0.f;
    if (t < Bc*2)  g_energy[t] = 0.f;
}

// ================= GEMM: q conv  X[b,c,s] x qw -> g_qT [bh][s][hd] =================
__global__ __launch_bounds__(256) void k_gemm_q(const float* __restrict__ X,
                                                const float* __restrict__ W,
                                                const float* __restrict__ bias)
{
    const int b  = blockIdx.z;
    const int o0 = blockIdx.y * 64;
    const int s0 = blockIdx.x * 64;
    const int tid = threadIdx.x;
    const int tx = tid & 15, ty = tid >> 4;

    __shared__ __align__(16) float sW[16][68];
    __shared__ __align__(16) float sX[16][68];
    __shared__ float sC[64][65];

    float acc[4][4] = {};
    const float* Xb = X + (size_t)b * CH * NS;

    for (int kk = 0; kk < CH; kk += 16) {
        {   // W transpose load: sW[c][o]
            int r = tid >> 2, cq = (tid & 3) * 4;
            float4 w4 = *(const float4*)&W[(o0 + r) * CH + kk + cq];
            sW[cq + 0][r] = w4.x; sW[cq + 1][r] = w4.y;
            sW[cq + 2][r] = w4.z; sW[cq + 3][r] = w4.w;
        }
        {   // X load: sX[c][s]
            int r = tid >> 4, cq = (tid & 15) * 4;
            *(float4*)&sX[r][cq] = *(const float4*)&Xb[(size_t)(kk + r) * NS + s0 + cq];
        }
        __syncthreads();
#pragma unroll
        for (int k = 0; k < 16; k++) {
            float4 av = *(const float4*)&sW[k][ty * 4];
            float4 bv = *(const float4*)&sX[k][tx * 4];
            acc[0][0] += av.x*bv.x; acc[0][1] += av.x*bv.y; acc[0][2] += av.x*bv.z; acc[0][3] += av.x*bv.w;
            acc[1][0] += av.y*bv.x; acc[1][1] += av.y*bv.y; acc[1][2] += av.y*bv.z; acc[1][3] += av.y*bv.w;
            acc[2][0] += av.z*bv.x; acc[2][1] += av.z*bv.y; acc[2][2] += av.z*bv.z; acc[2][3] += av.z*bv.w;
            acc[3][0] += av.w*bv.x; acc[3][1] += av.w*bv.y; acc[3][2] += av.w*bv.z; acc[3][3] += av.w*bv.w;
        }
        __syncthreads();
    }
#pragma unroll
    for (int i = 0; i < 4; i++) {
        float bv = bias[o0 + ty * 4 + i];
#pragma unroll
        for (int j = 0; j < 4; j++) sC[ty * 4 + i][tx * 4 + j] = acc[i][j] + bv;
    }
    __syncthreads();
#pragma unroll
    for (int it = 0; it < 16; ++it) {
        int idx = tid + it * 256;
        int sl = idx >> 6, ol = idx & 63;
        int o = o0 + ol;
        g_qT[(((size_t)b * NH + (o >> 5)) * NS + (s0 + sl)) * HD + (o & 31)] = sC[ol][sl];
    }
}

// ================= GEMM: fused k & v conv -> g_kvh half2 =================
__global__ __launch_bounds__(256) void k_gemm_kv(const float* __restrict__ X,
                                                 const float* __restrict__ Wk, const float* __restrict__ bk,
                                                 const float* __restrict__ Wv, const float* __restrict__ bv_)
{
    const int b  = blockIdx.z;
    const int o0 = blockIdx.y * 64;
    const int s0 = blockIdx.x * 64;
    const int tid = threadIdx.x;
    const int tx = tid & 15, ty = tid >> 4;

    __shared__ __align__(16) float sWk[16][68];
    __shared__ __align__(16) float sWv[16][68];
    __shared__ __align__(16) float sX[16][68];
    __shared__ __half2 sC2[64][65];

    float ak[4][4] = {}, av_[4][4] = {};
    const float* Xb = X + (size_t)b * CH * NS;

    for (int kk = 0; kk < CH; kk += 16) {
        {
            int r = tid >> 2, cq = (tid & 3) * 4;
            float4 w4 = *(const float4*)&Wk[(o0 + r) * CH + kk + cq];
            sWk[cq + 0][r] = w4.x; sWk[cq + 1][r] = w4.y; sWk[cq + 2][r] = w4.z; sWk[cq + 3][r] = w4.w;
            float4 v4 = *(const float4*)&Wv[(o0 + r) * CH + kk + cq];
            sWv[cq + 0][r] = v4.x; sWv[cq + 1][r] = v4.y; sWv[cq + 2][r] = v4.z; sWv[cq + 3][r] = v4.w;
        }
        {
            int r = tid >> 4, cq = (tid & 15) * 4;
            *(float4*)&sX[r][cq] = *(const float4*)&Xb[(size_t)(kk + r) * NS + s0 + cq];
        }
        __syncthreads();
#pragma unroll
        for (int k = 0; k < 16; k++) {
            float4 wa = *(const float4*)&sWk[k][ty * 4];
            float4 wb = *(const float4*)&sWv[k][ty * 4];
            float4 xv = *(const float4*)&sX[k][tx * 4];
            ak[0][0] += wa.x*xv.x; ak[0][1] += wa.x*xv.y; ak[0][2] += wa.x*xv.z; ak[0][3] += wa.x*xv.w;
            ak[1][0] += wa.y*xv.x; ak[1][1] += wa.y*xv.y; ak[1][2] += wa.y*xv.z; ak[1][3] += wa.y*xv.w;
            ak[2][0] += wa.z*xv.x; ak[2][1] += wa.z*xv.y; ak[2][2] += wa.z*xv.z; ak[2][3] += wa.z*xv.w;
            ak[3][0] += wa.w*xv.x; ak[3][1] += wa.w*xv.y; ak[3][2] += wa.w*xv.z; ak[3][3] += wa.w*xv.w;
            av_[0][0] += wb.x*xv.x; av_[0][1] += wb.x*xv.y; av_[0][2] += wb.x*xv.z; av_[0][3] += wb.x*xv.w;
            av_[1][0] += wb.y*xv.x; av_[1][1] += wb.y*xv.y; av_[1][2] += wb.y*xv.z; av_[1][3] += wb.y*xv.w;
            av_[2][0] += wb.z*xv.x; av_[2][1] += wb.z*xv.y; av_[2][2] += wb.z*xv.z; av_[2][3] += wb.z*xv.w;
            av_[3][0] += wb.w*xv.x; av_[3][1] += wb.w*xv.y; av_[3][2] += wb.w*xv.z; av_[3][3] += wb.w*xv.w;
        }
        __syncthreads();
    }
#pragma unroll
    for (int i = 0; i < 4; i++) {
        int o = o0 + ty * 4 + i;
        float bkk = bk[o], bvv = bv_[o];
#pragma unroll
        for (int j = 0; j < 4; j++)
            sC2[ty * 4 + i][tx * 4 + j] = __floats2half2_rn(ak[i][j] + bkk, av_[i][j] + bvv);
    }
    __syncthreads();
#pragma unroll
    for (int it = 0; it < 16; ++it) {
        int idx = tid + it * 256;
        int sl = idx >> 6, ol = idx & 63;
        int o = o0 + ol;
        g_kvh[(((size_t)b * NH + (o >> 5)) * NS + (s0 + sl)) * HD + (o & 31)] = sC2[ol][sl];
    }
}

// ================= depthwise 3x3x3 on qT -> tT & lepeT (x-register-blocked) =================
__global__ __launch_bounds__(256) void k_dwconv(const float* __restrict__ odw, const float* __restrict__ odb,
                                                const float* __restrict__ rpew, const float* __restrict__ rpeb)
{
    const int bh = blockIdx.y;
    const int h = bh % NH;
    const int lane = threadIdx.x & 31, wid = threadIdx.x >> 5;

    __shared__ float sWt[27][32];
    __shared__ float sWl[27][32];
    for (int idx = threadIdx.x; idx < 27 * 32; idx += 256) {
        int c = idx & 31, tap = idx >> 5;
        sWt[tap][c] = odw[(h * 32 + c) * 27 + tap];
        sWl[tap][c] = rpew[(h * 32 + c) * 27 + tap];
    }
    __syncthreads();

    const float bt = odb[h * 32 + lane];
    const float bl = rpeb[h * 32 + lane];
    const float* base = g_qT + (size_t)bh * NS * HD;

    const int s0 = blockIdx.x * 64 + wid * 8;   // 8 consecutive x
    const int z = s0 >> 10, y = (s0 >> 5) & 31, xb = s0 & 31;

    float at[8], al[8];
#pragma unroll
    for (int p = 0; p < 8; p++) { at[p] = bt; al[p] = bl; }

#pragma unroll
    for (int kd = 0; kd < 3; kd++) {
        int zz = z + kd - 1;
        if ((unsigned)zz >= (unsigned)Dz) continue;
#pragma unroll
        for (int kh = 0; kh < 3; kh++) {
            int yy = y + kh - 1;
            if ((unsigned)yy >= (unsigned)Hy) continue;
            const float* rowp = base + (size_t)(zz * 1024 + yy * 32) * 32 + lane;
            float w[10];
#pragma unroll
            for (int i = 0; i < 10; i++) {
                int xx = xb - 1 + i;
                w[i] = ((unsigned)xx < (unsigned)Wx) ? rowp[xx * 32] : 0.f;
            }
            const int t0 = (kd * 3 + kh) * 3;
            const float wt0 = sWt[t0][lane], wt1 = sWt[t0 + 1][lane], wt2 = sWt[t0 + 2][lane];
            const float wl0 = sWl[t0][lane], wl1 = sWl[t0 + 1][lane], wl2 = sWl[t0 + 2][lane];
#pragma unroll
            for (int p = 0; p < 8; p++) {
                at[p] += w[p] * wt0 + w[p + 1] * wt1 + w[p + 2] * wt2;
                al[p] += w[p] * wl0 + w[p + 1] * wl1 + w[p + 2] * wl2;
            }
        }
    }
#pragma unroll
    for (int p = 0; p < 8; p++) {
        size_t oi = ((size_t)bh * NS + s0 + p) * 32 + lane;
        g_tT[oi] = at[p];
        g_lepeT[oi] = al[p];
    }
}

// ================= LN + GELU + offset conv + tanh*scale =================
__global__ void k_offsets(const float* __restrict__ lnw, const float* __restrict__ lnb,
                          const float* __restrict__ opw, const float* __restrict__ opb,
                          float* __restrict__ d_out)
{
    __shared__ float sOp[18 * 192];
    __shared__ float sLn[2][192];
    for (int i = threadIdx.x; i < 18 * 192; i += 256) sOp[i] = opw[i];
    for (int i = threadIdx.x; i < 192; i += 256) { sLn[0][i] = lnw[i]; sLn[1][i] = lnb[i]; }
    __syncthreads();

    const int lane = threadIdx.x & 31, wid = threadIdx.x >> 5;
    const int gid = blockIdx.x * 8 + wid;
    const int b = gid >> 14;
    const int s = gid & (NS - 1);

    float v[6];
#pragma unroll
    for (int h = 0; h < 6; h++) v[h] = g_tT[(((size_t)b * 6 + h) * NS + s) * 32 + lane];

    float sm = 0.f;
#pragma unroll
    for (int h = 0; h < 6; h++) sm += v[h];
    sm = warpSum(sm);
    float mean = sm * (1.f / 192.f);
    float s2 = 0.f;
#pragma unroll
    for (int h = 0; h < 6; h++) { float d = v[h] - mean; s2 += d * d; }
    s2 = warpSum(s2);
    float inv = rsqrtf(s2 * (1.f / 192.f) + 1e-5f);

    float g[6];
#pragma unroll
    for (int h = 0; h < 6; h++) {
        int c = h * 32 + lane;
        float n = (v[h] - mean) * inv * sLn[0][c] + sLn[1][c];
        g[h] = 0.5f * n * (1.f + erff(n * 0.70710678118654752f));
    }

    // 18 independent partial sums, then stage-major butterfly so shuffles pipeline
    float p18[18];
#pragma unroll
    for (int o = 0; o < 18; o++) {
        float p = 0.f;
#pragma unroll
        for (int h = 0; h < 6; h++) p += g[h] * sOp[o * 192 + h * 32 + lane];
        p18[o] = p;
    }
#pragma unroll
    for (int o = 16; o; o >>= 1)
#pragma unroll
        for (int j = 0; j < 18; j++) p18[j] += __shfl_xor_sync(0xffffffffu, p18[j], o);

    float mine = 0.f;
#pragma unroll
    for (int j = 0; j < 18; j++) if (lane == j) mine = p18[j];

    float ov = 0.f;
    if (lane < 18) {
        float val = tanhf(mine + opb[lane]);
        int comp = lane % 3;
        float sc = (comp == 2) ? (2.f / 15.f) : (2.f / 31.f);
        ov = val * sc;
        int h = lane / 3;
        size_t oi = (((size_t)b * 6 + h) * NS + s) * 3 + comp;
        g_offs[oi] = ov;
        d_out[O_OFFS + oi] = ov;
    }
    float ox = __shfl_sync(0xffffffffu, ov, (lane < 6) ? 3 * lane : 0);
    float oy = __shfl_sync(0xffffffffu, ov, (lane < 6) ? 3 * lane + 1 : 0);
    float oz = __shfl_sync(0xffffffffu, ov, (lane < 6) ? 3 * lane + 2 : 0);
    if (lane < 6) atomicAdd(&g_mag[b * 6 + lane], sqrtf(ox * ox + oy * oy + oz * oz));
}

// ================= attention epilogue (shared by both branches) =================
__device__ __forceinline__ void attn_epilogue(float res, int b, int h, int bi,
                                              int lane, int wid, int s0b, size_t qi)
{
    float outv = res + g_lepeT[qi];
    __shared__ float sT[8][33];
    __shared__ float sE[8];
    sT[wid][lane] = outv;
    float e = warpSum(fabsf(res));
    if (lane == 0) sE[wid] = e;
    __syncthreads();
    int ch = threadIdx.x >> 3, si = threadIdx.x & 7;
    g_attnC[((size_t)b * CH + h * 32 + ch) * NS + s0b + si] = sT[si][ch];
    if (threadIdx.x == 0) {
        float t = 0.f;
#pragma unroll
        for (int i = 0; i < 8; i++) t += sE[i];
        atomicAdd(&g_energy[b * 2 + bi], t);
    }
}

// ================= attention branch 0 (dil=1): shared 4x4x4 lattice =================
__global__ __launch_bounds__(256) void k_attn1(const float* __restrict__ bias0)
{
    const int bhh = blockIdx.y;
    const int b = bhh / 3, hh = bhh % 3;
    const int h = hh;
    const int bh = b * NH + h;
    const float* bias = bias0 + hh * 27;

    const int lane = threadIdx.x & 31, wid = threadIdx.x >> 5;
    const int s0b = blockIdx.x * 8;
    const int s = s0b + wid;
    const int z = s >> 10, y = (s >> 5) & 31, x = s & 31;

    const size_t qi = ((size_t)bh * NS + s) * 32 + lane;
    const float q = g_qT[qi];
    const float* ob = g_offs + ((size_t)bh * NS + s) * 3;
    const float bx = (float)x + ob[0] * 15.5f;
    const float by = (float)y + ob[1] * 15.5f;
    const float bz = (float)z + ob[2] * 7.5f;

    const __half2* __restrict__ kv = g_kvh + (size_t)bh * NS * HD;

    float fx = floorf(bx), fy = floorf(by), fz = floorf(bz);
    int X0 = (int)fx, Y0 = (int)fy, Z0 = (int)fz;
    float wx = bx - fx, wy = by - fy, wz = bz - fz;
    float uz = 1.f - wz;

    int LXo[4], LYo[4], LZo[4];
#pragma unroll
    for (int t = 0; t < 4; t++) {
        LXo[t] = min(max(X0 - 1 + t, 0), 31) * 32 + lane;
        LYo[t] = min(max(Y0 - 1 + t, 0), 31) * 1024;
        LZo[t] = min(max(Z0 - 1 + t, 0), 15) * 32768;
    }

    float2 zacc[27];
#pragma unroll
    for (int j = 0; j < 27; j++) zacc[j] = make_float2(0.f, 0.f);

#pragma unroll
    for (int tz = 0; tz < 4; tz++) {
        float2 P[4][4];
#pragma unroll
        for (int ty = 0; ty < 4; ty++)
#pragma unroll
            for (int tx = 0; tx < 4; tx++)
                P[ty][tx] = __half22float2(kv[LZo[tz] + LYo[ty] + LXo[tx]]);
        // x-lerp
        float2 A[4][3];
#pragma unroll
        for (int ty = 0; ty < 4; ty++)
#pragma unroll
            for (int jx = 0; jx < 3; jx++) {
                A[ty][jx].x = P[ty][jx].x + wx * (P[ty][jx + 1].x - P[ty][jx].x);
                A[ty][jx].y = P[ty][jx].y + wx * (P[ty][jx + 1].y - P[ty][jx].y);
            }
        // y-lerp
        float2 Bv[3][3];
#pragma unroll
        for (int jy = 0; jy < 3; jy++)
#pragma unroll
            for (int jx = 0; jx < 3; jx++) {
                Bv[jy][jx].x = A[jy][jx].x + wy * (A[jy + 1][jx].x - A[jy][jx].x);
                Bv[jy][jx].y = A[jy][jx].y + wy * (A[jy + 1][jx].y - A[jy][jx].y);
            }
        // z-accumulate
        if (tz < 3) {
#pragma unroll
            for (int r = 0; r < 9; r++) {
                zacc[tz * 9 + r].x += uz * Bv[r / 3][r % 3].x;
                zacc[tz * 9 + r].y += uz * Bv[r / 3][r % 3].y;
            }
        }
        if (tz > 0) {
#pragma unroll
            for (int r = 0; r < 9; r++) {
                zacc[(tz - 1) * 9 + r].x += wz * Bv[r / 3][r % 3].x;
                zacc[(tz - 1) * 9 + r].y += wz * Bv[r / 3][r % 3].y;
            }
        }
    }

    float sc[27];
#pragma unroll
    for (int j = 0; j < 27; j++) sc[j] = q * zacc[j].x;
#pragma unroll
    for (int o = 16; o; o >>= 1)
#pragma unroll
        for (int j = 0; j < 27; j++) sc[j] += __shfl_xor_sync(0xffffffffu, sc[j], o);

    float m = -1e30f;
#pragma unroll
    for (int j = 0; j < 27; j++) { sc[j] = sc[j] * SCALE + bias[j]; m = fmaxf(m, sc[j]); }
    float l = 0.f, acc = 0.f;
#pragma unroll
    for (int j = 0; j < 27; j++) {
        float p = __expf(sc[j] - m);
        l += p;
        acc += p * zacc[j].y;
    }
    attn_epilogue(acc / l, b, h, 0, lane, wid, s0b, qi);
}

// ================= attention branch 1 (dil=2): direct 8-corner =================
__global__ __launch_bounds__(256) void k_attn2(const float* __restrict__ bias1)
{
    const int bhh = blockIdx.y;
    const int b = bhh / 3, hh = bhh % 3;
    const int h = hh + 3;
    const int bh = b * NH + h;
    const float* bias = bias1 + hh * 27;

    const int lane = threadIdx.x & 31, wid = threadIdx.x >> 5;
    const int s0b = blockIdx.x * 8;
    const int s = s0b + wid;
    const int z = s >> 10, y = (s >> 5) & 31, x = s & 31;

    const size_t qi = ((size_t)bh * NS + s) * 32 + lane;
    const float q = g_qT[qi];
    const float* ob = g_offs + ((size_t)bh * NS + s) * 3;
    const float bx = (float)x + ob[0] * 15.5f;
    const float by = (float)y + ob[1] * 15.5f;
    const float bz = (float)z + ob[2] * 7.5f;

    const __half2* __restrict__ kv = g_kvh + (size_t)bh * NS * HD;

    float sc[27], vs[27];
#pragma unroll
    for (int j = 0; j < 27; j++) {
        const int rx = (j % 3 - 1) * 2;
        const int ry = ((j / 3) % 3 - 1) * 2;
        const int rz = (j / 9 - 1) * 2;
        float px = fminf(fmaxf(bx + rx, 0.f), 31.f);
        float py = fminf(fmaxf(by + ry, 0.f), 31.f);
        float pz = fminf(fmaxf(bz + rz, 0.f), 15.f);
        float fx = floorf(px), fy = floorf(py), fz = floorf(pz);
        int x0 = (int)fx, y0 = (int)fy, z0 = (int)fz;
        int x1 = min(x0 + 1, 31), y1 = min(y0 + 1, 31), z1 = min(z0 + 1, 15);
        float wx = px - fx, wy = py - fy, wz = pz - fz;
        float ux = 1.f - wx, uy = 1.f - wy, uz = 1.f - wz;

        int r00 = (z0 * 32 + y0) * 1024, r01 = (z0 * 32 + y1) * 1024;
        int r10 = (z1 * 32 + y0) * 1024, r11 = (z1 * 32 + y1) * 1024;
        int cx0 = x0 * 32 + lane, cx1 = x1 * 32 + lane;

        float2 c000 = __half22float2(kv[r00 + cx0]), c001 = __half22float2(kv[r00 + cx1]);
        float2 c010 = __half22float2(kv[r01 + cx0]), c011 = __half22float2(kv[r01 + cx1]);
        float2 c100 = __half22float2(kv[r10 + cx0]), c101 = __half22float2(kv[r10 + cx1]);
        float2 c110 = __half22float2(kv[r11 + cx0]), c111 = __half22float2(kv[r11 + cx1]);

        float w00 = uz * uy, w01 = uz * wy, w10 = wz * uy, w11 = wz * wy;
        float w000 = w00 * ux, w001 = w00 * wx, w010 = w01 * ux, w011 = w01 * wx;
        float w100 = w10 * ux, w101 = w10 * wx, w110 = w11 * ux, w111 = w11 * wx;

        float ks = w000 * c000.x + w001 * c001.x + w010 * c010.x + w011 * c011.x
                 + w100 * c100.x + w101 * c101.x + w110 * c110.x + w111 * c111.x;
        float vv = w000 * c000.y + w001 * c001.y + w010 * c010.y + w011 * c011.y
                 + w100 * c100.y + w101 * c101.y + w110 * c110.y + w111 * c111.y;
        sc[j] = q * ks;
        vs[j] = vv;
    }
#pragma unroll
    for (int o = 16; o; o >>= 1)
#pragma unroll
        for (int j = 0; j < 27; j++) sc[j] += __shfl_xor_sync(0xffffffffu, sc[j], o);

    float m = -1e30f;
#pragma unroll
    for (int j = 0; j < 27; j++) { sc[j] = sc[j] * SCALE + bias[j]; m = fmaxf(m, sc[j]); }
    float l = 0.f, acc = 0.f;
#pragma unroll
    for (int j = 0; j < 27; j++) {
        float p = __expf(sc[j] - m);
        l += p;
        acc += p * vs[j];
    }
    attn_epilogue(acc / l, b, h, 1, lane, wid, s0b, qi);
}

// ================= final conv: g_attnC [b,c,s] x pw -> out [b,c,s] =================
__global__ __launch_bounds__(256) void k_gemm_final(const float* __restrict__ W,
                                                    const float* __restrict__ bias,
                                                    float* __restrict__ out)
{
    const int b  = blockIdx.z;
    const int o0 = blockIdx.y * 64;
    const int s0 = blockIdx.x * 64;
    const int tid = threadIdx.x;
    const int tx = tid & 15, ty = tid >> 4;

    __shared__ __align__(16) float sW[16][68];
    __shared__ __align__(16) float sX[16][68];

    float acc[4][4] = {};
    const float* Xb = g_attnC + (size_t)b * CH * NS;

    for (int kk = 0; kk < CH; kk += 16) {
        {
            int r = tid >> 2, cq = (tid & 3) * 4;
            float4 w4 = *(const float4*)&W[(o0 + r) * CH + kk + cq];
            sW[cq + 0][r] = w4.x; sW[cq + 1][r] = w4.y;
            sW[cq + 2][r] = w4.z; sW[cq + 3][r] = w4.w;
        }
        {
            int r = tid >> 4, cq = (tid & 15) * 4;
            *(float4*)&sX[r][cq] = *(const float4*)&Xb[(size_t)(kk + r) * NS + s0 + cq];
        }
        __syncthreads();
#pragma unroll
        for (int k = 0; k < 16; k++) {
            float4 av = *(const float4*)&sW[k][ty * 4];
            float4 bv = *(const float4*)&sX[k][tx * 4];
            acc[0][0] += av.x*bv.x; acc[0][1] += av.x*bv.y; acc[0][2] += av.x*bv.z; acc[0][3] += av.x*bv.w;
            acc[1][0] += av.y*bv.x; acc[1][1] += av.y*bv.y; acc[1][2] += av.y*bv.z; acc[1][3] += av.y*bv.w;
            acc[2][0] += av.z*bv.x; acc[2][1] += av.z*bv.y; acc[2][2] += av.z*bv.z; acc[2][3] += av.z*bv.w;
            acc[3][0] += av.w*bv.x; acc[3][1] += av.w*bv.y; acc[3][2] += av.w*bv.z; acc[3][3] += av.w*bv.w;
        }
        __syncthreads();
    }
#pragma unroll
    for (int i = 0; i < 4; i++) {
        int o = o0 + ty * 4 + i;
        float bv = bias[o];
        float4 r = make_float4(acc[i][0] + bv, acc[i][1] + bv, acc[i][2] + bv, acc[i][3] + bv);
        *(float4*)&out[O_OUT + ((size_t)b * CH + o) * NS + s0 + tx * 4] = r;
    }
}

__global__ void k_finalize(float* __restrict__ out)
{
    int t = threadIdx.x;
    const float inv_sp = 1.f / (float)NS;
    const float inv_en = 1.f / (3.f * 32.f * (float)NS);
    if (t < 12) out[O_MAG + t] = g_mag[t] * inv_sp;
    if (t < 4)  out[O_EN + t] = g_energy[t] * inv_en;
    if (t < 16) {
        int b = t >> 3, j = t & 7;
        out[O_GUIDE + t] = (j < 6) ? g_mag[b * 6 + j] * inv_sp
                                   : g_energy[b * 2 + (j - 6)] * inv_en;
    }
}

extern "C" void kernel_launch(void* const* d_in, const int* in_sizes, int n_in,
                              void* d_out, int out_size)
{
    const float* x    = (const float*)d_in[0];
    const float* qw   = (const float*)d_in[1];
    const float* qb   = (const float*)d_in[2];
    const float* kw   = (const float*)d_in[3];
    const float* kbi  = (const float*)d_in[4];
    const float* vw   = (const float*)d_in[5];
    const float* vbi  = (const float*)d_in[6];
    const float* pw   = (const float*)d_in[7];
    const float* pb   = (const float*)d_in[8];
    const float* odw  = (const float*)d_in[9];
    const float* odb  = (const float*)d_in[10];
    const float* lnw  = (const float*)d_in[11];
    const float* lnb  = (const float*)d_in[12];
    const float* opw  = (const float*)d_in[13];
    const float* opb  = (const float*)d_in[14];
    const float* rpew = (const float*)d_in[15];
    const float* rpeb = (const float*)d_in[16];
    const float* b0   = (const float*)d_in[17];
    const float* b1   = (const float*)d_in[18];
    float* out = (float*)d_out;

    k_zero<<<1, 32>>>();

    dim3 gG(NS / 64, CH / 64, Bc);
    k_gemm_q<<<gG, 256>>>(x, qw, qb);
    k_gemm_kv<<<gG, 256>>>(x, kw, kbi, vw, vbi);

    k_dwconv<<<dim3(NS / 64, Bc * NH), 256>>>(odw, odb, rpew, rpeb);
    k_offsets<<<dim3(Bc * NS / 8), 256>>>(lnw, lnb, opw, opb, out);

    k_attn1<<<dim3(NS / 8, Bc * 3), 256>>>(b0);
    k_attn2<<<dim3(NS / 8, Bc * 3), 256>>>(b1);

    k_gemm_final<<<gG, 256>>>(pw, pb, out);
    k_finalize<<<1, 32>>>(out);
}

// round 8
// speedup vs baseline: 1.9099x; 1.0124x over previous
#include <cuda_runtime.h>
#include <cuda_bf16.h>
#include <cuda_fp16.h>
#include <math.h>

#define Bc 2
#define NH 6
#define HD 32
#define Dz 16
#define Hy 32
#define Wx 32
#define NS (Dz*Hy*Wx)      // 16384
#define CH 192
#define SCALE 0.17677669529663687f

// Output regions (tuple concat): out, offs, offset_mag, branch_energy, guide
#define O_OUT   0
#define O_OFFS  6291456     // 2*192*16384
#define O_MAG   6881280     // + 2*6*16384*3
#define O_EN    6881292
#define O_GUIDE 6881296

// Scratch (device globals; allocation-free)
__device__ float   g_qT[Bc*NH*NS*HD];      // [bh][s][hd]
__device__ __half2 g_kvh[Bc*NH*NS*HD];     // [bh][s][hd] -> (k, v) fp16
__device__ float   g_tT[Bc*NH*NS*HD];
__device__ float   g_lepeT[Bc*NH*NS*HD];
__device__ float   g_attnC[Bc*CH*NS];      // [b][c][s]  (attn + lepe)
__device__ float   g_offs[Bc*NH*NS*3];
__device__ float   g_mag[Bc*NH];
__device__ float   g_energy[Bc*2];

__device__ __forceinline__ float warpSum(float v) {
#pragma unroll
    for (int o = 16; o; o >>= 1) v += __shfl_xor_sync(0xffffffffu, v, o);
    return v;
}

__global__ void k_zero() {
    int t = threadIdx.x;
    if (t < Bc*NH) g_mag[t] = 0.f;
    if (t < Bc*2)  g_energy[t] = 0.f;
}

// ================= GEMM: q conv  X[b,c,s] x qw -> g_qT [bh][s][hd] =================
__global__ __launch_bounds__(256) void k_gemm_q(const float* __restrict__ X,
                                                const float* __restrict__ W,
                                                const float* __restrict__ bias)
{
    const int b  = blockIdx.z;
    const int o0 = blockIdx.y * 64;
    const int s0 = blockIdx.x * 64;
    const int tid = threadIdx.x;
    const int tx = tid & 15, ty = tid >> 4;

    __shared__ __align__(16) float sW[16][68];
    __shared__ __align__(16) float sX[16][68];
    __shared__ float sC[64][65];

    float acc[4][4] = {};
    const float* Xb = X + (size_t)b * CH * NS;

    for (int kk = 0; kk < CH; kk += 16) {
        {   // W transpose load: sW[c][o]
            int r = tid >> 2, cq = (tid & 3) * 4;
            float4 w4 = *(const float4*)&W[(o0 + r) * CH + kk + cq];
            sW[cq + 0][r] = w4.x; sW[cq + 1][r] = w4.y;
            sW[cq + 2][r] = w4.z; sW[cq + 3][r] = w4.w;
        }
        {   // X load: sX[c][s]
            int r = tid >> 4, cq = (tid & 15) * 4;
            *(float4*)&sX[r][cq] = *(const float4*)&Xb[(size_t)(kk + r) * NS + s0 + cq];
        }
        __syncthreads();
#pragma unroll
        for (int k = 0; k < 16; k++) {
            float4 av = *(const float4*)&sW[k][ty * 4];
            float4 bv = *(const float4*)&sX[k][tx * 4];
            acc[0][0] += av.x*bv.x; acc[0][1] += av.x*bv.y; acc[0][2] += av.x*bv.z; acc[0][3] += av.x*bv.w;
            acc[1][0] += av.y*bv.x; acc[1][1] += av.y*bv.y; acc[1][2] += av.y*bv.z; acc[1][3] += av.y*bv.w;
            acc[2][0] += av.z*bv.x; acc[2][1] += av.z*bv.y; acc[2][2] += av.z*bv.z; acc[2][3] += av.z*bv.w;
            acc[3][0] += av.w*bv.x; acc[3][1] += av.w*bv.y; acc[3][2] += av.w*bv.z; acc[3][3] += av.w*bv.w;
        }
        __syncthreads();
    }
#pragma unroll
    for (int i = 0; i < 4; i++) {
        float bv = bias[o0 + ty * 4 + i];
#pragma unroll
        for (int j = 0; j < 4; j++) sC[ty * 4 + i][tx * 4 + j] = acc[i][j] + bv;
    }
    __syncthreads();
#pragma unroll
    for (int it = 0; it < 16; ++it) {
        int idx = tid + it * 256;
        int sl = idx >> 6, ol = idx & 63;
        int o = o0 + ol;
        g_qT[(((size_t)b * NH + (o >> 5)) * NS + (s0 + sl)) * HD + (o & 31)] = sC[ol][sl];
    }
}

// ================= GEMM: fused k & v conv -> g_kvh half2 =================
__global__ __launch_bounds__(256) void k_gemm_kv(const float* __restrict__ X,
                                                 const float* __restrict__ Wk, const float* __restrict__ bk,
                                                 const float* __restrict__ Wv, const float* __restrict__ bv_)
{
    const int b  = blockIdx.z;
    const int o0 = blockIdx.y * 64;
    const int s0 = blockIdx.x * 64;
    const int tid = threadIdx.x;
    const int tx = tid & 15, ty = tid >> 4;

    __shared__ __align__(16) float sWk[16][68];
    __shared__ __align__(16) float sWv[16][68];
    __shared__ __align__(16) float sX[16][68];
    __shared__ __half2 sC2[64][65];

    float ak[4][4] = {}, av_[4][4] = {};
    const float* Xb = X + (size_t)b * CH * NS;

    for (int kk = 0; kk < CH; kk += 16) {
        {
            int r = tid >> 2, cq = (tid & 3) * 4;
            float4 w4 = *(const float4*)&Wk[(o0 + r) * CH + kk + cq];
            sWk[cq + 0][r] = w4.x; sWk[cq + 1][r] = w4.y; sWk[cq + 2][r] = w4.z; sWk[cq + 3][r] = w4.w;
            float4 v4 = *(const float4*)&Wv[(o0 + r) * CH + kk + cq];
            sWv[cq + 0][r] = v4.x; sWv[cq + 1][r] = v4.y; sWv[cq + 2][r] = v4.z; sWv[cq + 3][r] = v4.w;
        }
        {
            int r = tid >> 4, cq = (tid & 15) * 4;
            *(float4*)&sX[r][cq] = *(const float4*)&Xb[(size_t)(kk + r) * NS + s0 + cq];
        }
        __syncthreads();
#pragma unroll
        for (int k = 0; k < 16; k++) {
            float4 wa = *(const float4*)&sWk[k][ty * 4];
            float4 wb = *(const float4*)&sWv[k][ty * 4];
            float4 xv = *(const float4*)&sX[k][tx * 4];
            ak[0][0] += wa.x*xv.x; ak[0][1] += wa.x*xv.y; ak[0][2] += wa.x*xv.z; ak[0][3] += wa.x*xv.w;
            ak[1][0] += wa.y*xv.x; ak[1][1] += wa.y*xv.y; ak[1][2] += wa.y*xv.z; ak[1][3] += wa.y*xv.w;
            ak[2][0] += wa.z*xv.x; ak[2][1] += wa.z*xv.y; ak[2][2] += wa.z*xv.z; ak[2][3] += wa.z*xv.w;
            ak[3][0] += wa.w*xv.x; ak[3][1] += wa.w*xv.y; ak[3][2] += wa.w*xv.z; ak[3][3] += wa.w*xv.w;
            av_[0][0] += wb.x*xv.x; av_[0][1] += wb.x*xv.y; av_[0][2] += wb.x*xv.z; av_[0][3] += wb.x*xv.w;
            av_[1][0] += wb.y*xv.x; av_[1][1] += wb.y*xv.y; av_[1][2] += wb.y*xv.z; av_[1][3] += wb.y*xv.w;
            av_[2][0] += wb.z*xv.x; av_[2][1] += wb.z*xv.y; av_[2][2] += wb.z*xv.z; av_[2][3] += wb.z*xv.w;
            av_[3][0] += wb.w*xv.x; av_[3][1] += wb.w*xv.y; av_[3][2] += wb.w*xv.z; av_[3][3] += wb.w*xv.w;
        }
        __syncthreads();
    }
#pragma unroll
    for (int i = 0; i < 4; i++) {
        int o = o0 + ty * 4 + i;
        float bkk = bk[o], bvv = bv_[o];
#pragma unroll
        for (int j = 0; j < 4; j++)
            sC2[ty * 4 + i][tx * 4 + j] = __floats2half2_rn(ak[i][j] + bkk, av_[i][j] + bvv);
    }
    __syncthreads();
#pragma unroll
    for (int it = 0; it < 16; ++it) {
        int idx = tid + it * 256;
        int sl = idx >> 6, ol = idx & 63;
        int o = o0 + ol;
        g_kvh[(((size_t)b * NH + (o >> 5)) * NS + (s0 + sl)) * HD + (o & 31)] = sC2[ol][sl];
    }
}

// ================= depthwise 3x3x3 on qT -> tT & lepeT (x-register-blocked) =================
__global__ __launch_bounds__(256) void k_dwconv(const float* __restrict__ odw, const float* __restrict__ odb,
                                                const float* __restrict__ rpew, const float* __restrict__ rpeb)
{
    const int bh = blockIdx.y;
    const int h = bh % NH;
    const int lane = threadIdx.x & 31, wid = threadIdx.x >> 5;

    __shared__ float sWt[27][32];
    __shared__ float sWl[27][32];
    for (int idx = threadIdx.x; idx < 27 * 32; idx += 256) {
        int c = idx & 31, tap = idx >> 5;
        sWt[tap][c] = odw[(h * 32 + c) * 27 + tap];
        sWl[tap][c] = rpew[(h * 32 + c) * 27 + tap];
    }
    __syncthreads();

    const float bt = odb[h * 32 + lane];
    const float bl = rpeb[h * 32 + lane];
    const float* base = g_qT + (size_t)bh * NS * HD;

    const int s0 = blockIdx.x * 64 + wid * 8;   // 8 consecutive x
    const int z = s0 >> 10, y = (s0 >> 5) & 31, xb = s0 & 31;

    float at[8], al[8];
#pragma unroll
    for (int p = 0; p < 8; p++) { at[p] = bt; al[p] = bl; }

#pragma unroll
    for (int kd = 0; kd < 3; kd++) {
        int zz = z + kd - 1;
        if ((unsigned)zz >= (unsigned)Dz) continue;
#pragma unroll
        for (int kh = 0; kh < 3; kh++) {
            int yy = y + kh - 1;
            if ((unsigned)yy >= (unsigned)Hy) continue;
            const float* rowp = base + (size_t)(zz * 1024 + yy * 32) * 32 + lane;
            float w[10];
#pragma unroll
            for (int i = 0; i < 10; i++) {
                int xx = xb - 1 + i;
                w[i] = ((unsigned)xx < (unsigned)Wx) ? rowp[xx * 32] : 0.f;
            }
            const int t0 = (kd * 3 + kh) * 3;
            const float wt0 = sWt[t0][lane], wt1 = sWt[t0 + 1][lane], wt2 = sWt[t0 + 2][lane];
            const float wl0 = sWl[t0][lane], wl1 = sWl[t0 + 1][lane], wl2 = sWl[t0 + 2][lane];
#pragma unroll
            for (int p = 0; p < 8; p++) {
                at[p] += w[p] * wt0 + w[p + 1] * wt1 + w[p + 2] * wt2;
                al[p] += w[p] * wl0 + w[p + 1] * wl1 + w[p + 2] * wl2;
            }
        }
    }
#pragma unroll
    for (int p = 0; p < 8; p++) {
        size_t oi = ((size_t)bh * NS + s0 + p) * 32 + lane;
        g_tT[oi] = at[p];
        g_lepeT[oi] = al[p];
    }
}

// ================= LN + GELU + offset conv + tanh*scale =================
__global__ void k_offsets(const float* __restrict__ lnw, const float* __restrict__ lnb,
                          const float* __restrict__ opw, const float* __restrict__ opb,
                          float* __restrict__ d_out)
{
    __shared__ float sOp[18 * 192];
    __shared__ float sLn[2][192];
    for (int i = threadIdx.x; i < 18 * 192; i += 256) sOp[i] = opw[i];
    for (int i = threadIdx.x; i < 192; i += 256) { sLn[0][i] = lnw[i]; sLn[1][i] = lnb[i]; }
    __syncthreads();

    const int lane = threadIdx.x & 31, wid = threadIdx.x >> 5;
    const int gid = blockIdx.x * 8 + wid;
    const int b = gid >> 14;
    const int s = gid & (NS - 1);

    float v[6];
#pragma unroll
    for (int h = 0; h < 6; h++) v[h] = g_tT[(((size_t)b * 6 + h) * NS + s) * 32 + lane];

    float sm = 0.f;
#pragma unroll
    for (int h = 0; h < 6; h++) sm += v[h];
    sm = warpSum(sm);
    float mean = sm * (1.f / 192.f);
    float s2 = 0.f;
#pragma unroll
    for (int h = 0; h < 6; h++) { float d = v[h] - mean; s2 += d * d; }
    s2 = warpSum(s2);
    float inv = rsqrtf(s2 * (1.f / 192.f) + 1e-5f);

    float g[6];
#pragma unroll
    for (int h = 0; h < 6; h++) {
        int c = h * 32 + lane;
        float n = (v[h] - mean) * inv * sLn[0][c] + sLn[1][c];
        g[h] = 0.5f * n * (1.f + erff(n * 0.70710678118654752f));
    }

    float p18[18];
#pragma unroll
    for (int o = 0; o < 18; o++) {
        float p = 0.f;
#pragma unroll
        for (int h = 0; h < 6; h++) p += g[h] * sOp[o * 192 + h * 32 + lane];
        p18[o] = p;
    }
#pragma unroll
    for (int o = 16; o; o >>= 1)
#pragma unroll
        for (int j = 0; j < 18; j++) p18[j] += __shfl_xor_sync(0xffffffffu, p18[j], o);

    float mine = 0.f;
#pragma unroll
    for (int j = 0; j < 18; j++) if (lane == j) mine = p18[j];

    float ov = 0.f;
    if (lane < 18) {
        float val = tanhf(mine + opb[lane]);
        int comp = lane % 3;
        float sc = (comp == 2) ? (2.f / 15.f) : (2.f / 31.f);
        ov = val * sc;
        int h = lane / 3;
        size_t oi = (((size_t)b * 6 + h) * NS + s) * 3 + comp;
        g_offs[oi] = ov;
        d_out[O_OFFS + oi] = ov;
    }
    float ox = __shfl_sync(0xffffffffu, ov, (lane < 6) ? 3 * lane : 0);
    float oy = __shfl_sync(0xffffffffu, ov, (lane < 6) ? 3 * lane + 1 : 0);
    float oz = __shfl_sync(0xffffffffu, ov, (lane < 6) ? 3 * lane + 2 : 0);
    if (lane < 6) atomicAdd(&g_mag[b * 6 + lane], sqrtf(ox * ox + oy * oy + oz * oz));
}

// ================= attention epilogue (shared by both branches) =================
__device__ __forceinline__ void attn_epilogue(float res, int b, int h, int bi,
                                              int lane, int wid, int s0b, size_t qi)
{
    float outv = res + g_lepeT[qi];
    __shared__ float sT[8][33];
    __shared__ float sE[8];
    sT[wid][lane] = outv;
    float e = warpSum(fabsf(res));
    if (lane == 0) sE[wid] = e;
    __syncthreads();
    int ch = threadIdx.x >> 3, si = threadIdx.x & 7;
    g_attnC[((size_t)b * CH + h * 32 + ch) * NS + s0b + si] = sT[si][ch];
    if (threadIdx.x == 0) {
        float t = 0.f;
#pragma unroll
        for (int i = 0; i < 8; i++) t += sE[i];
        atomicAdd(&g_energy[b * 2 + bi], t);
    }
}

// ================= shared softmax tail over 27 (sc partials, val.y payload) =========
__device__ __forceinline__ float softmax27(float* sc, const float2* zacc, const float* bias, float q)
{
#pragma unroll
    for (int o = 16; o; o >>= 1)
#pragma unroll
        for (int j = 0; j < 27; j++) sc[j] += __shfl_xor_sync(0xffffffffu, sc[j], o);
    float m = -1e30f;
#pragma unroll
    for (int j = 0; j < 27; j++) { sc[j] = sc[j] * SCALE + bias[j]; m = fmaxf(m, sc[j]); }
    float l = 0.f, acc = 0.f;
#pragma unroll
    for (int j = 0; j < 27; j++) {
        float p = __expf(sc[j] - m);
        l += p;
        acc += p * zacc[j].y;
    }
    return acc / l;
}

// ================= attention branch 0 (dil=1): shared 4x4x4 lattice =================
__global__ __launch_bounds__(256) void k_attn1(const float* __restrict__ bias0)
{
    const int bhh = blockIdx.y;
    const int b = bhh / 3, hh = bhh % 3;
    const int h = hh;
    const int bh = b * NH + h;
    const float* bias = bias0 + hh * 27;

    const int lane = threadIdx.x & 31, wid = threadIdx.x >> 5;
    const int s0b = blockIdx.x * 8;
    const int s = s0b + wid;
    const int z = s >> 10, y = (s >> 5) & 31, x = s & 31;

    const size_t qi = ((size_t)bh * NS + s) * 32 + lane;
    const float q = g_qT[qi];
    const float* ob = g_offs + ((size_t)bh * NS + s) * 3;
    const float bx = (float)x + ob[0] * 15.5f;
    const float by = (float)y + ob[1] * 15.5f;
    const float bz = (float)z + ob[2] * 7.5f;

    const __half2* __restrict__ kv = g_kvh + (size_t)bh * NS * HD;

    float fx = floorf(bx), fy = floorf(by), fz = floorf(bz);
    int X0 = (int)fx, Y0 = (int)fy, Z0 = (int)fz;
    float wx = bx - fx, wy = by - fy, wz = bz - fz;
    float uz = 1.f - wz;

    int LXo[4], LYo[4], LZo[4];
#pragma unroll
    for (int t = 0; t < 4; t++) {
        LXo[t] = min(max(X0 - 1 + t, 0), 31) * 32 + lane;
        LYo[t] = min(max(Y0 - 1 + t, 0), 31) * 1024;
        LZo[t] = min(max(Z0 - 1 + t, 0), 15) * 32768;
    }

    float2 zacc[27];
#pragma unroll
    for (int j = 0; j < 27; j++) zacc[j] = make_float2(0.f, 0.f);

#pragma unroll
    for (int tz = 0; tz < 4; tz++) {
        float2 P[4][4];
#pragma unroll
        for (int ty = 0; ty < 4; ty++)
#pragma unroll
            for (int tx = 0; tx < 4; tx++)
                P[ty][tx] = __half22float2(kv[LZo[tz] + LYo[ty] + LXo[tx]]);
        float2 A[4][3];
#pragma unroll
        for (int ty = 0; ty < 4; ty++)
#pragma unroll
            for (int jx = 0; jx < 3; jx++) {
                A[ty][jx].x = P[ty][jx].x + wx * (P[ty][jx + 1].x - P[ty][jx].x);
                A[ty][jx].y = P[ty][jx].y + wx * (P[ty][jx + 1].y - P[ty][jx].y);
            }
        float2 Bv[3][3];
#pragma unroll
        for (int jy = 0; jy < 3; jy++)
#pragma unroll
            for (int jx = 0; jx < 3; jx++) {
                Bv[jy][jx].x = A[jy][jx].x + wy * (A[jy + 1][jx].x - A[jy][jx].x);
                Bv[jy][jx].y = A[jy][jx].y + wy * (A[jy + 1][jx].y - A[jy][jx].y);
            }
        if (tz < 3) {
#pragma unroll
            for (int r = 0; r < 9; r++) {
                zacc[tz * 9 + r].x += uz * Bv[r / 3][r % 3].x;
                zacc[tz * 9 + r].y += uz * Bv[r / 3][r % 3].y;
            }
        }
        if (tz > 0) {
#pragma unroll
            for (int r = 0; r < 9; r++) {
                zacc[(tz - 1) * 9 + r].x += wz * Bv[r / 3][r % 3].x;
                zacc[(tz - 1) * 9 + r].y += wz * Bv[r / 3][r % 3].y;
            }
        }
    }

    float sc[27];
#pragma unroll
    for (int j = 0; j < 27; j++) sc[j] = q * zacc[j].x;
    float res = softmax27(sc, zacc, bias, q);
    attn_epilogue(res, b, h, 0, lane, wid, s0b, qi);
}

// ============ attention branch 1 (dil=2): separable disjoint 6x6x6 lattice ============
__global__ __launch_bounds__(256) void k_attn2(const float* __restrict__ bias1)
{
    const int bhh = blockIdx.y;
    const int b = bhh / 3, hh = bhh % 3;
    const int h = hh + 3;
    const int bh = b * NH + h;
    const float* bias = bias1 + hh * 27;

    const int lane = threadIdx.x & 31, wid = threadIdx.x >> 5;
    const int s0b = blockIdx.x * 8;
    const int s = s0b + wid;
    const int z = s >> 10, y = (s >> 5) & 31, x = s & 31;

    const size_t qi = ((size_t)bh * NS + s) * 32 + lane;
    const float q = g_qT[qi];
    const float* ob = g_offs + ((size_t)bh * NS + s) * 3;
    const float bx = (float)x + ob[0] * 15.5f;
    const float by = (float)y + ob[1] * 15.5f;
    const float bz = (float)z + ob[2] * 7.5f;

    const __half2* __restrict__ kv = g_kvh + (size_t)bh * NS * HD;

    float fx = floorf(bx), fy = floorf(by), fz = floorf(bz);
    int X0 = (int)fx, Y0 = (int)fy, Z0 = (int)fz;
    float wx = bx - fx, wy = by - fy, wz = bz - fz;
    float uz = 1.f - wz;

    // lattice X0-2 .. X0+3 (taps at rx=-2,0,2; corners tile the lattice disjointly)
    int LXo[6], LYo[6], LZo[6];
#pragma unroll
    for (int t = 0; t < 6; t++) {
        LXo[t] = min(max(X0 - 2 + t, 0), 31) * 32 + lane;
        LYo[t] = min(max(Y0 - 2 + t, 0), 31) * 1024;
        LZo[t] = min(max(Z0 - 2 + t, 0), 15) * 32768;
    }

    float2 zacc[27];
#pragma unroll
    for (int j = 0; j < 27; j++) zacc[j] = make_float2(0.f, 0.f);

#pragma unroll
    for (int tz = 0; tz < 6; tz++) {
        // load 6x6 plane, x-lerp on the fly (pairs 0-1, 2-3, 4-5)
        float2 A[6][3];
#pragma unroll
        for (int ty = 0; ty < 6; ty++)
#pragma unroll
            for (int jx = 0; jx < 3; jx++) {
                float2 a = __half22float2(kv[LZo[tz] + LYo[ty] + LXo[2 * jx]]);
                float2 c = __half22float2(kv[LZo[tz] + LYo[ty] + LXo[2 * jx + 1]]);
                A[ty][jx].x = a.x + wx * (c.x - a.x);
                A[ty][jx].y = a.y + wx * (c.y - a.y);
            }
        // y-lerp (pairs 0-1, 2-3, 4-5)
        float2 Bv[3][3];
#pragma unroll
        for (int jy = 0; jy < 3; jy++)
#pragma unroll
            for (int jx = 0; jx < 3; jx++) {
                Bv[jy][jx].x = A[2 * jy][jx].x + wy * (A[2 * jy + 1][jx].x - A[2 * jy][jx].x);
                Bv[jy][jx].y = A[2 * jy][jx].y + wy * (A[2 * jy + 1][jx].y - A[2 * jy][jx].y);
            }
        // z accumulate: tap jz = tz/2, weight uz for even tz, wz for odd
        const int jz = tz >> 1;
        const float wzz = (tz & 1) ? wz : uz;
#pragma unroll
        for (int r = 0; r < 9; r++) {
            zacc[jz * 9 + r].x += wzz * Bv[r / 3][r % 3].x;
            zacc[jz * 9 + r].y += wzz * Bv[r / 3][r % 3].y;
        }
    }

    float sc[27];
#pragma unroll
    for (int j = 0; j < 27; j++) sc[j] = q * zacc[j].x;
    float res = softmax27(sc, zacc, bias, q);
    attn_epilogue(res, b, h, 1, lane, wid, s0b, qi);
}

// ================= final conv: g_attnC [b,c,s] x pw -> out [b,c,s] =================
__global__ __launch_bounds__(256) void k_gemm_final(const float* __restrict__ W,
                                                    const float* __restrict__ bias,
                                                    float* __restrict__ out)
{
    const int b  = blockIdx.z;
    const int o0 = blockIdx.y * 64;
    const int s0 = blockIdx.x * 64;
    const int tid = threadIdx.x;
    const int tx = tid & 15, ty = tid >> 4;

    __shared__ __align__(16) float sW[16][68];
    __shared__ __align__(16) float sX[16][68];

    float acc[4][4] = {};
    const float* Xb = g_attnC + (size_t)b * CH * NS;

    for (int kk = 0; kk < CH; kk += 16) {
        {
            int r = tid >> 2, cq = (tid & 3) * 4;
            float4 w4 = *(const float4*)&W[(o0 + r) * CH + kk + cq];
            sW[cq + 0][r] = w4.x; sW[cq + 1][r] = w4.y;
            sW[cq + 2][r] = w4.z; sW[cq + 3][r] = w4.w;
        }
        {
            int r = tid >> 4, cq = (tid & 15) * 4;
            *(float4*)&sX[r][cq] = *(const float4*)&Xb[(size_t)(kk + r) * NS + s0 + cq];
        }
        __syncthreads();
#pragma unroll
        for (int k = 0; k < 16; k++) {
            float4 av = *(const float4*)&sW[k][ty * 4];
            float4 bv = *(const float4*)&sX[k][tx * 4];
            acc[0][0] += av.x*bv.x; acc[0][1] += av.x*bv.y; acc[0][2] += av.x*bv.z; acc[0][3] += av.x*bv.w;
            acc[1][0] += av.y*bv.x; acc[1][1] += av.y*bv.y; acc[1][2] += av.y*bv.z; acc[1][3] += av.y*bv.w;
            acc[2][0] += av.z*bv.x; acc[2][1] += av.z*bv.y; acc[2][2] += av.z*bv.z; acc[2][3] += av.z*bv.w;
            acc[3][0] += av.w*bv.x; acc[3][1] += av.w*bv.y; acc[3][2] += av.w*bv.z; acc[3][3] += av.w*bv.w;
        }
        __syncthreads();
    }
#pragma unroll
    for (int i = 0; i < 4; i++) {
        int o = o0 + ty * 4 + i;
        float bv = bias[o];
        float4 r = make_float4(acc[i][0] + bv, acc[i][1] + bv, acc[i][2] + bv, acc[i][3] + bv);
        *(float4*)&out[O_OUT + ((size_t)b * CH + o) * NS + s0 + tx * 4] = r;
    }
}

__global__ void k_finalize(float* __restrict__ out)
{
    int t = threadIdx.x;
    const float inv_sp = 1.f / (float)NS;
    const float inv_en = 1.f / (3.f * 32.f * (float)NS);
    if (t < 12) out[O_MAG + t] = g_mag[t] * inv_sp;
    if (t < 4)  out[O_EN + t] = g_energy[t] * inv_en;
    if (t < 16) {
        int b = t >> 3, j = t & 7;
        out[O_GUIDE + t] = (j < 6) ? g_mag[b * 6 + j] * inv_sp
                                   : g_energy[b * 2 + (j - 6)] * inv_en;
    }
}

extern "C" void kernel_launch(void* const* d_in, const int* in_sizes, int n_in,
                              void* d_out, int out_size)
{
    const float* x    = (const float*)d_in[0];
    const float* qw   = (const float*)d_in[1];
    const float* qb   = (const float*)d_in[2];
    const float* kw   = (const float*)d_in[3];
    const float* kbi  = (const float*)d_in[4];
    const float* vw   = (const float*)d_in[5];
    const float* vbi  = (const float*)d_in[6];
    const float* pw   = (const float*)d_in[7];
    const float* pb   = (const float*)d_in[8];
    const float* odw  = (const float*)d_in[9];
    const float* odb  = (const float*)d_in[10];
    const float* lnw  = (const float*)d_in[11];
    const float* lnb  = (const float*)d_in[12];
    const float* opw  = (const float*)d_in[13];
    const float* opb  = (const float*)d_in[14];
    const float* rpew = (const float*)d_in[15];
    const float* rpeb = (const float*)d_in[16];
    const float* b0   = (const float*)d_in[17];
    const float* b1   = (const float*)d_in[18];
    float* out = (float*)d_out;

    k_zero<<<1, 32>>>();

    dim3 gG(NS / 64, CH / 64, Bc);
    k_gemm_q<<<gG, 256>>>(x, qw, qb);
    k_gemm_kv<<<gG, 256>>>(x, kw, kbi, vw, vbi);

    k_dwconv<<<dim3(NS / 64, Bc * NH), 256>>>(odw, odb, rpew, rpeb);
    k_offsets<<<dim3(Bc * NS / 8), 256>>>(lnw, lnb, opw, opb, out);

    k_attn1<<<dim3(NS / 8, Bc * 3), 256>>>(b0);
    k_attn2<<<dim3(NS / 8, Bc * 3), 256>>>(b1);

    k_gemm_final<<<gG, 256>>>(pw, pb, out);
    k_finalize<<<1, 32>>>(out);
}